// round 12
// baseline (speedup 1.0000x reference)
#include <cuda_runtime.h>
#include <cuda_bf16.h>
#include <math.h>
#include <stdint.h>

// Problem constants
#define BATCH 256
#define SEQ   200
#define DIM   300
#define NHEAD 6
#define DHEAD 50
#define NROW  (BATCH*SEQ)        // 51200
#define LDH   320
#define LDF   608
#define GELU_C 0.7978845608028654f

// ---------------- scratch (device globals; zero-initialized) ------------------
__device__ float g_sin[SEQ*DIM];
__device__ float g_h  [NROW*LDH];          // residual stream (fp32)
__device__ float g_h1 [NROW*LDH];          // post-LN1 (fp32)
__device__ float g_prj[NROW*LDH];
__device__ float g_ff2[NROW*LDH];
__device__ float g_s1 [NROW];
__device__ unsigned char g_mask[NROW];

__device__ __nv_bfloat16 g_qkvb[NROW*900]; // QKV activations (bf16)
__device__ __nv_bfloat16 g_hb [NROW*LDH];
__device__ __nv_bfloat16 g_h1b[NROW*LDH];
__device__ __nv_bfloat16 g_att[NROW*LDH];
__device__ __nv_bfloat16 g_ff1[NROW*LDF];

// packed bf16 weights: word w[kp][n] = {B[2kp][n], B[2kp+1][n]}, zero padded
#define QKV_W (160*1024)
#define PRJ_W (160*384)
#define FF1_W (160*640)
#define FF2_W (304*384)
__device__ uint32_t g_pw_qkv[5*QKV_W];
__device__ uint32_t g_pw_prj[5*PRJ_W];
__device__ uint32_t g_pw_ff1[5*FF1_W];
__device__ uint32_t g_pw_ff2[5*FF2_W];

__device__ __forceinline__ float gelu_f(float x) {
    float x3 = x*x*x;
    return 0.5f*x*(1.0f + tanhf(GELU_C*(x + 0.044715f*x3)));
}
__device__ __forceinline__ uint32_t smemu32(const void* p) {
    return (uint32_t)__cvta_generic_to_shared(p);
}
#define CP16(dst, src) asm volatile("cp.async.cg.shared.global [%0], [%1], 16;\n" :: "r"(dst), "l"(src))
#define CP_COMMIT()    asm volatile("cp.async.commit_group;\n" ::)
#define CP_WAIT(N)     asm volatile("cp.async.wait_group %0;\n" :: "n"(N))

#define MMA_BF16(acc, a0,a1,a2,a3, b0,b1) \
    asm volatile( \
        "mma.sync.aligned.m16n8k16.row.col.f32.bf16.bf16.f32 " \
        "{%0,%1,%2,%3}, {%4,%5,%6,%7}, {%8,%9}, {%0,%1,%2,%3};" \
        : "+f"((acc)[0]), "+f"((acc)[1]), "+f"((acc)[2]), "+f"((acc)[3]) \
        : "r"(a0), "r"(a1), "r"(a2), "r"(a3), "r"(b0), "r"(b1))

// ---------------- sinusoid table ----------------------------------------------
__global__ void sin_table_kernel() {
    int idx = blockIdx.x*blockDim.x + threadIdx.x;
    if (idx >= SEQ*DIM) return;
    int pos = idx / DIM, i = idx % DIM;
    double ang = (double)pos / pow(10000.0, 2.0*(double)(i/2)/(double)DIM);
    g_sin[idx] = (float)((i & 1) ? cos(ang) : sin(ang));
}

// ---------------- embedding + pos-enc + initial mask --------------------------
__global__ void embed_kernel(const int* __restrict__ tok,
                             const float* __restrict__ emb) {
    int idx = blockIdx.x*blockDim.x + threadIdx.x;
    if (idx >= NROW*DIM) return;
    int r = idx / DIM, d = idx % DIM;
    int t = tok[r];
    float v = emb[(size_t)t*DIM + d];
    if (t != 0) v += g_sin[(r % SEQ)*DIM + d];
    g_h [(size_t)r*LDH + d] = v;
    g_hb[(size_t)r*LDH + d] = __float2bfloat16_rn(v);
    if (d == 0) g_mask[r] = (t == 0) ? 1 : 0;
}

// ---------------- weight packing ----------------------------------------------
__device__ __forceinline__ void pack_bf(const float* __restrict__ src,
                                        uint32_t* __restrict__ dst, int i,
                                        int K, int N, int Kpw, int Np) {
    int per = Kpw*Np;
    int l = i / per, r = i % per;
    int kp = r / Np, n = r % Np;
    float f0 = (2*kp   < K && n < N) ? src[(size_t)l*K*N + (size_t)(2*kp  )*N + n] : 0.0f;
    float f1 = (2*kp+1 < K && n < N) ? src[(size_t)l*K*N + (size_t)(2*kp+1)*N + n] : 0.0f;
    __nv_bfloat162 p = __floats2bfloat162_rn(f0, f1);
    dst[i] = *reinterpret_cast<uint32_t*>(&p);
}
__global__ void pack_all_kernel(const float* __restrict__ qkv_w,
                                const float* __restrict__ out_w,
                                const float* __restrict__ ff1_w,
                                const float* __restrict__ ff2_w) {
    int i = blockIdx.x*blockDim.x + threadIdx.x;
    if (i < 5*QKV_W) { pack_bf(qkv_w, g_pw_qkv, i, 300, 900, 160, 1024); return; }
    i -= 5*QKV_W;
    if (i < 5*PRJ_W) { pack_bf(out_w, g_pw_prj, i, 300, 300, 160, 384); return; }
    i -= 5*PRJ_W;
    if (i < 5*FF1_W) { pack_bf(ff1_w, g_pw_ff1, i, 300, 600, 160, 640); return; }
    i -= 5*FF1_W;
    if (i < 5*FF2_W) { pack_bf(ff2_w, g_pw_ff2, i, 600, 300, 304, 384); return; }
}

// ---------------- BF16 tensor-core GEMM (5-stage, single-sync) ----------------
#define BM 128
#define BN 128
#define STAGES 5
#define ASTRIDE 20
#define BSTRIDE 136
#define A_ELEMS (BM*ASTRIDE)
#define B_ELEMS (16*BSTRIDE)
#define GEMM_SMEM ((STAGES*(A_ELEMS + B_ELEMS))*4)   // 94720 bytes

__global__ __launch_bounds__(256, 2) void mma_gemm_kernel(
        const __nv_bfloat16* __restrict__ A, const uint32_t* __restrict__ Bw,
        const float* __restrict__ bias, void* __restrict__ Cv,
        int N, int Kp, int lda, int Np, int ldc, int act, int obf) {
    extern __shared__ uint32_t dsm[];
    uint32_t* Asm = dsm;
    uint32_t* Bsm = dsm + STAGES*A_ELEMS;

    int tid = threadIdx.x;
    int warp = tid >> 5, lane = tid & 31;
    int g = lane >> 2, tig = lane & 3;
    int mw = (warp >> 2)*64, nw = (warp & 3)*32;
    int bm = blockIdx.y*BM, bn = blockIdx.x*BN;

    const __nv_bfloat16* Abase = A + (size_t)bm*lda;
    const uint32_t* Bbase = Bw + bn;

    float acc[4][4][4];
    #pragma unroll
    for (int i = 0; i < 4; i++)
        #pragma unroll
        for (int j = 0; j < 4; j++)
            #pragma unroll
            for (int r = 0; r < 4; r++) acc[i][j][r] = 0.0f;

    int nIter = Kp / 32;
    int am0 = tid >> 2,          awc0 = (tid & 3)*4;
    int am1 = (tid + 256) >> 2;
    int bk0 = tid >> 5,          bnc0 = (tid & 31)*4;
    int bk1 = (tid + 256) >> 5;

    auto loadStage = [&](int it, int s) {
        int k0e = it*32, k0w = it*16;
        uint32_t* As = Asm + s*A_ELEMS;
        uint32_t* Bs = Bsm + s*B_ELEMS;
        CP16(smemu32(&As[am0*ASTRIDE + awc0]), Abase + (size_t)am0*lda + k0e + awc0*2);
        CP16(smemu32(&As[am1*ASTRIDE + awc0]), Abase + (size_t)am1*lda + k0e + awc0*2);
        CP16(smemu32(&Bs[bk0*BSTRIDE + bnc0]), Bbase + (size_t)(k0w+bk0)*Np + bnc0);
        CP16(smemu32(&Bs[bk1*BSTRIDE + bnc0]), Bbase + (size_t)(k0w+bk1)*Np + bnc0);
    };

    #pragma unroll
    for (int s = 0; s < STAGES-1; s++) {
        loadStage(s, s);
        CP_COMMIT();
    }

    int cur = 0;
    for (int it = 0; it < nIter; it++) {
        CP_WAIT(STAGES-2);
        __syncthreads();

        const uint32_t* As = Asm + cur*A_ELEMS;
        const uint32_t* Bs = Bsm + cur*B_ELEMS;
        #pragma unroll
        for (int ks = 0; ks < 2; ks++) {
            int kb = ks*8;
            uint32_t af[4][4], bf[4][2];
            #pragma unroll
            for (int mt = 0; mt < 4; mt++) {
                int rm = mw + mt*16;
                af[mt][0] = As[(rm + g    )*ASTRIDE + kb + tig    ];
                af[mt][1] = As[(rm + g + 8)*ASTRIDE + kb + tig    ];
                af[mt][2] = As[(rm + g    )*ASTRIDE + kb + tig + 4];
                af[mt][3] = As[(rm + g + 8)*ASTRIDE + kb + tig + 4];
            }
            #pragma unroll
            for (int nt = 0; nt < 4; nt++) {
                int cn = nw + nt*8;
                bf[nt][0] = Bs[(kb + tig    )*BSTRIDE + cn + g];
                bf[nt][1] = Bs[(kb + tig + 4)*BSTRIDE + cn + g];
            }
            #pragma unroll
            for (int mt = 0; mt < 4; mt++)
                #pragma unroll
                for (int nt = 0; nt < 4; nt++)
                    MMA_BF16(acc[mt][nt], af[mt][0], af[mt][1], af[mt][2], af[mt][3],
                             bf[nt][0], bf[nt][1]);
        }

        if (it + STAGES-1 < nIter) {
            int s = (it + STAGES-1) % STAGES;
            loadStage(it + STAGES-1, s);
        }
        CP_COMMIT();
        cur = (cur + 1 == STAGES) ? 0 : cur + 1;
    }

    #pragma unroll
    for (int mt = 0; mt < 4; mt++) {
        int row0 = bm + mw + mt*16 + g;
        #pragma unroll
        for (int nt = 0; nt < 4; nt++) {
            int col = bn + nw + nt*8 + tig*2;
            if (col < N) {
                float b0 = bias[col], b1 = bias[col+1];
                float v0 = acc[mt][nt][0] + b0;
                float v1 = acc[mt][nt][1] + b1;
                float v2 = acc[mt][nt][2] + b0;
                float v3 = acc[mt][nt][3] + b1;
                if (act == 1) { v0 = gelu_f(v0); v1 = gelu_f(v1); v2 = gelu_f(v2); v3 = gelu_f(v3); }
                if (obf) {
                    __nv_bfloat16* C16 = (__nv_bfloat16*)Cv;
                    __nv_bfloat162 pa = __floats2bfloat162_rn(v0, v1);
                    __nv_bfloat162 pb = __floats2bfloat162_rn(v2, v3);
                    *(__nv_bfloat162*)&C16[(size_t)row0*ldc + col]     = pa;
                    *(__nv_bfloat162*)&C16[(size_t)(row0+8)*ldc + col] = pb;
                } else {
                    float* C = (float*)Cv;
                    *(float2*)&C[(size_t)row0*ldc + col]     = make_float2(v0, v1);
                    *(float2*)&C[(size_t)(row0+8)*ldc + col] = make_float2(v2, v3);
                }
            }
        }
    }
}

// ---------------- bf16 tensor-core attention ----------------------------------
// One block per (qchunk, b*h). All of K^T, V, Q-chunk resident in smem as bf16
// words; single fill phase; fp32 softmax; bf16 m16n8k16 for S and P@V.
#define AQS 36      // Qs[64 rows][36 kwords]       (4g+tig conflict-free)
#define KTS 216     // Kt[32 kwords][216 keys]      (24tig+g conflict-free)
#define VSS 72      // Vs[104 kwords][72 d]         (8tig+g conflict-free)
#define PSS 212     // Ps fp32 [64][212]
#define PBS 108     // Pb[64 rows][108 kwords]      (12g+tig conflict-free)
#define AQ_E (64*AQS)
#define KT_E (32*KTS)
#define VS_E (104*VSS)
#define PS_E (64*PSS)
#define PB_E (64*PBS)
#define ATTN_SMEM ((AQ_E + KT_E + VS_E + PS_E + PB_E + 64)*4 + 256)

__global__ __launch_bounds__(256) void attn_kernel(
        const __nv_bfloat16* __restrict__ qkv,
        const unsigned char* __restrict__ mask,
        __nv_bfloat16* __restrict__ out) {
    extern __shared__ uint32_t smw[];
    uint32_t* Qs = smw;
    uint32_t* Kt = Qs + AQ_E;
    uint32_t* Vs = Kt + KT_E;
    float*    Ps = (float*)(Vs + VS_E);
    uint32_t* Pb = (uint32_t*)(Ps + PS_E);
    float*    inv = (float*)(Pb + PB_E);
    unsigned char* mk = (unsigned char*)(inv + 64);

    int bh = blockIdx.y;
    int b = bh / NHEAD, h = bh % NHEAD;
    int qbase = blockIdx.x * 64;
    int tid = threadIdx.x;
    int warp = tid >> 5, lane = tid & 31;
    int g = lane >> 2, tig = lane & 3;
    int wm = (warp >> 1)*16;
    int wn = warp & 1;

    const float scale = 0.1414213562373095f;  // 1/sqrt(50)
    // word-view of qkv rows: row r, element e -> word (r*900+e)/2 (e even)
    const uint32_t* qw = (const uint32_t*)qkv;
    size_t rowbase = (size_t)b*SEQ*450;       // word offset of row 0

    if (tid < SEQ) mk[tid] = mask[b*SEQ + tid];
    int padcnt = __syncthreads_count(tid < SEQ && mask[b*SEQ + tid]);
    bool allpad = (padcnt == SEQ);

    // ---- single fill phase ----
    // Q chunk: 64 rows x 32 kwords (25 data)
    for (int i = tid; i < 64*32; i += 256) {
        int r = i >> 5, wc = i & 31;
        int q = qbase + r;
        uint32_t v = (wc < 25 && q < SEQ) ? qw[rowbase + (size_t)q*450 + h*25 + wc] : 0u;
        Qs[r*AQS + wc] = v;
    }
    // K^T: 32 kwords x 208 keys (coalesced loads; 4-way smem store conflict OK)
    for (int i = tid; i < 32*208; i += 256) {
        int kw = i & 31, key = i >> 5;
        uint32_t v = (kw < 25 && key < SEQ) ? qw[rowbase + (size_t)key*450 + 150 + h*25 + kw] : 0u;
        Kt[kw*KTS + key] = v;
    }
    // V: word[kw][d] = {V[2kw][d], V[2kw+1][d]} (key-pair pack)
    for (int i = tid; i < 104*64; i += 256) {
        int d = i & 63, kw = i >> 6;
        uint32_t v = 0;
        if (d < DHEAD) {
            int k0 = 2*kw, k1 = 2*kw + 1;
            uint32_t lo = (k0 < SEQ) ? *(const uint16_t*)(qkv + (size_t)(b*SEQ + k0)*900 + 600 + h*DHEAD + d) : 0;
            uint32_t hi = (k1 < SEQ) ? *(const uint16_t*)(qkv + (size_t)(b*SEQ + k1)*900 + 600 + h*DHEAD + d) : 0;
            v = lo | (hi << 16);
        }
        Vs[kw*VSS + d] = v;
    }
    __syncthreads();

    // ---- S = Q @ K^T (m16n8k16): M=64, N=208, K=64 elems (32 kwords) ----
    {
        float sacc[13][4];
        #pragma unroll
        for (int nt = 0; nt < 13; nt++)
            #pragma unroll
            for (int r = 0; r < 4; r++) sacc[nt][r] = 0.0f;
        #pragma unroll
        for (int ks = 0; ks < 4; ks++) {
            int kb = ks*8;
            uint32_t a0 = Qs[(wm + g    )*AQS + kb + tig    ];
            uint32_t a1 = Qs[(wm + g + 8)*AQS + kb + tig    ];
            uint32_t a2 = Qs[(wm + g    )*AQS + kb + tig + 4];
            uint32_t a3 = Qs[(wm + g + 8)*AQS + kb + tig + 4];
            #pragma unroll
            for (int nt = 0; nt < 13; nt++) {
                int cn = wn*104 + nt*8;
                uint32_t b0 = Kt[(kb + tig    )*KTS + cn + g];
                uint32_t b1 = Kt[(kb + tig + 4)*KTS + cn + g];
                MMA_BF16(sacc[nt], a0, a1, a2, a3, b0, b1);
            }
        }
        #pragma unroll
        for (int nt = 0; nt < 13; nt++) {
            int col = wn*104 + nt*8 + tig*2;
            *(float2*)&Ps[(wm + g    )*PSS + col] = make_float2(sacc[nt][0], sacc[nt][1]);
            *(float2*)&Ps[(wm + g + 8)*PSS + col] = make_float2(sacc[nt][2], sacc[nt][3]);
        }
    }
    __syncthreads();

    // ---- fp32 softmax; thread j handles contiguous run [j*52, j*52+52) ----
    {
        int row = tid >> 2, j = tid & 3;
        int k0r = j*52;
        float m = -INFINITY;
        for (int k = k0r; k < k0r + 52; k++)
            if (k < SEQ && !mk[k]) m = fmaxf(m, Ps[row*PSS + k]*scale);
        m = fmaxf(m, __shfl_xor_sync(0xffffffffu, m, 1));
        m = fmaxf(m, __shfl_xor_sync(0xffffffffu, m, 2));
        float ssum = 0.0f;
        for (int kw = j*26; kw < j*26 + 26; kw++) {
            int ka = 2*kw, kb2 = 2*kw + 1;
            float p0 = 0.0f, p1 = 0.0f;
            if (ka  < SEQ && !mk[ka])  { p0 = __expf(Ps[row*PSS + ka ]*scale - m); ssum += p0; }
            if (kb2 < SEQ && !mk[kb2]) { p1 = __expf(Ps[row*PSS + kb2]*scale - m); ssum += p1; }
            __nv_bfloat162 pp = __floats2bfloat162_rn(p0, p1);
            Pb[row*PBS + kw] = *reinterpret_cast<uint32_t*>(&pp);
        }
        ssum += __shfl_xor_sync(0xffffffffu, ssum, 1);
        ssum += __shfl_xor_sync(0xffffffffu, ssum, 2);
        if (j == 0) inv[row] = (allpad || ssum == 0.0f) ? 0.0f : 1.0f/ssum;
    }
    __syncthreads();

    // ---- O = P @ V (m16n8k16): M=64, N=64, K=208 (104 kwords) ----
    {
        float oacc[4][4];
        #pragma unroll
        for (int nt = 0; nt < 4; nt++)
            #pragma unroll
            for (int r = 0; r < 4; r++) oacc[nt][r] = 0.0f;
        #pragma unroll
        for (int ks = 0; ks < 13; ks++) {
            int kb = ks*8;
            uint32_t a0 = Pb[(wm + g    )*PBS + kb + tig    ];
            uint32_t a1 = Pb[(wm + g + 8)*PBS + kb + tig    ];
            uint32_t a2 = Pb[(wm + g    )*PBS + kb + tig + 4];
            uint32_t a3 = Pb[(wm + g + 8)*PBS + kb + tig + 4];
            #pragma unroll
            for (int nt = 0; nt < 4; nt++) {
                int cn = wn*32 + nt*8;
                uint32_t b0 = Vs[(kb + tig    )*VSS + cn + g];
                uint32_t b1 = Vs[(kb + tig + 4)*VSS + cn + g];
                MMA_BF16(oacc[nt], a0, a1, a2, a3, b0, b1);
            }
        }
        float v0 = inv[wm + g], v1 = inv[wm + g + 8];
        int q0 = qbase + wm + g;
        #pragma unroll
        for (int nt = 0; nt < 4; nt++) {
            int col = wn*32 + nt*8 + tig*2;
            if (col < DHEAD) {
                if (q0 < SEQ) {
                    __nv_bfloat162 p = __floats2bfloat162_rn(oacc[nt][0]*v0, oacc[nt][1]*v0);
                    *(__nv_bfloat162*)&out[(size_t)(b*SEQ + q0)*LDH + h*DHEAD + col] = p;
                }
                if (q0 + 8 < SEQ) {
                    __nv_bfloat162 p = __floats2bfloat162_rn(oacc[nt][2]*v1, oacc[nt][3]*v1);
                    *(__nv_bfloat162*)&out[(size_t)(b*SEQ + q0 + 8)*LDH + h*DHEAD + col] = p;
                }
            }
        }
    }
}

// ---------------- warp-per-row residual add + LayerNorm -----------------------
__global__ void ln_kernel(const float* __restrict__ X,
                          const float* __restrict__ Y,
                          const float* __restrict__ s,
                          const float* __restrict__ bcoef,
                          float* __restrict__ out,
                          __nv_bfloat16* __restrict__ outb,
                          unsigned char* maskout) {
    int tid = threadIdx.x, warp = tid >> 5, lane = tid & 31;
    int r = blockIdx.x*8 + warp;
    if (r >= NROW) return;

    float v[10]; int nd = 0;
    float sum = 0.0f;
    for (int d = lane; d < DIM; d += 32) {
        float t = X[(size_t)r*LDH + d] + Y[(size_t)r*LDH + d];
        v[nd++] = t;
        sum += t;
    }
    #pragma unroll
    for (int off = 16; off > 0; off >>= 1) sum += __shfl_xor_sync(0xffffffffu, sum, off);
    float mean = sum / (float)DIM;

    float var = 0.0f;
    for (int i = 0; i < nd; i++) { float d0 = v[i] - mean; var += d0*d0; }
    #pragma unroll
    for (int off = 16; off > 0; off >>= 1) var += __shfl_xor_sync(0xffffffffu, var, off);
    float rstd = 1.0f / sqrtf(var/(float)DIM + 1e-5f);

    bool allz = true;
    int i2 = 0;
    for (int d = lane; d < DIM; d += 32) {
        float o = (v[i2++] - mean)*rstd*s[d] + bcoef[d];
        out[(size_t)r*LDH + d] = o;
        outb[(size_t)r*LDH + d] = __float2bfloat16_rn(o);
        if (o != 0.0f) allz = false;
    }
    if (maskout) {
        bool all = __all_sync(0xffffffffu, allz);
        if (lane == 0) maskout[r] = all ? 1 : 0;
    }
}

// ---------------- head kernels ------------------------------------------------
__global__ void rowdot_kernel(const float* __restrict__ w1,
                              const float* __restrict__ b1) {
    int tid = threadIdx.x, warp = tid >> 5, lane = tid & 31;
    int r = blockIdx.x*8 + warp;
    if (r >= NROW) return;
    float acc = 0.0f;
    for (int d = lane; d < DIM; d += 32)
        acc += g_h[(size_t)r*LDH + d] * w1[d];
    #pragma unroll
    for (int off = 16; off > 0; off >>= 1) acc += __shfl_xor_sync(0xffffffffu, acc, off);
    if (lane == 0) g_s1[r] = acc + b1[0];
}

__global__ void head_kernel(const float* __restrict__ w2, const float* __restrict__ b2,
                            const float* __restrict__ wo, const float* __restrict__ bo,
                            const float* __restrict__ wa, const float* __restrict__ ba,
                            float* __restrict__ out) {
    __shared__ float s1s[SEQ];
    __shared__ float s2s[50];
    int b = blockIdx.x, tid = threadIdx.x;
    for (int i = tid; i < SEQ; i += 64) s1s[i] = g_s1[b*SEQ + i];
    __syncthreads();
    if (tid < 50) {
        float acc = 0.0f;
        for (int s = 0; s < SEQ; s++) acc += s1s[s]*w2[s*50 + tid];
        s2s[tid] = gelu_f(acc + b2[tid]);
    }
    __syncthreads();
    if (tid < 7) {
        float acc = 0.0f;
        if (tid == 0) {
            for (int i = 0; i < 50; i++) acc += s2s[i]*wo[i];
            out[b*7] = acc + bo[0];
        } else {
            int j = tid - 1;
            for (int i = 0; i < 50; i++) acc += s2s[i]*wa[i*6 + j];
            out[b*7 + tid] = acc + ba[j];
        }
    }
}

// ---------------- launch ------------------------------------------------------
extern "C" void kernel_launch(void* const* d_in, const int* in_sizes, int n_in,
                              void* d_out, int out_size) {
    const int*   x_tok  = (const int*)  d_in[0];
    const float* emb    = (const float*)d_in[1];
    const float* qkv_w  = (const float*)d_in[2];
    const float* qkv_b  = (const float*)d_in[3];
    const float* out_w  = (const float*)d_in[4];
    const float* out_b  = (const float*)d_in[5];
    const float* ln1_s  = (const float*)d_in[6];
    const float* ln1_b  = (const float*)d_in[7];
    const float* ff1_w  = (const float*)d_in[8];
    const float* ff1_b  = (const float*)d_in[9];
    const float* ff2_w  = (const float*)d_in[10];
    const float* ff2_b  = (const float*)d_in[11];
    const float* ln2_s  = (const float*)d_in[12];
    const float* ln2_b  = (const float*)d_in[13];
    const float* lin1_w = (const float*)d_in[14];
    const float* lin1_b = (const float*)d_in[15];
    const float* lin2_w = (const float*)d_in[16];
    const float* lin2_b = (const float*)d_in[17];
    const float* lout_w = (const float*)d_in[18];
    const float* lout_b = (const float*)d_in[19];
    const float* laux_w = (const float*)d_in[20];
    const float* laux_b = (const float*)d_in[21];

    float *p_h, *p_h1, *p_prj, *p_ff2;
    __nv_bfloat16 *p_qkvb, *p_hb, *p_h1b, *p_att, *p_ff1;
    uint32_t *p_wqkv, *p_wprj, *p_wff1, *p_wff2;
    unsigned char *p_mask;
    cudaGetSymbolAddress((void**)&p_h,    g_h);
    cudaGetSymbolAddress((void**)&p_h1,   g_h1);
    cudaGetSymbolAddress((void**)&p_prj,  g_prj);
    cudaGetSymbolAddress((void**)&p_ff2,  g_ff2);
    cudaGetSymbolAddress((void**)&p_qkvb, g_qkvb);
    cudaGetSymbolAddress((void**)&p_hb,   g_hb);
    cudaGetSymbolAddress((void**)&p_h1b,  g_h1b);
    cudaGetSymbolAddress((void**)&p_att,  g_att);
    cudaGetSymbolAddress((void**)&p_ff1,  g_ff1);
    cudaGetSymbolAddress((void**)&p_mask, g_mask);
    cudaGetSymbolAddress((void**)&p_wqkv, g_pw_qkv);
    cudaGetSymbolAddress((void**)&p_wprj, g_pw_prj);
    cudaGetSymbolAddress((void**)&p_wff1, g_pw_ff1);
    cudaGetSymbolAddress((void**)&p_wff2, g_pw_ff2);

    cudaFuncSetAttribute(attn_kernel, cudaFuncAttributeMaxDynamicSharedMemorySize,
                         ATTN_SMEM);
    cudaFuncSetAttribute(mma_gemm_kernel, cudaFuncAttributeMaxDynamicSharedMemorySize,
                         GEMM_SMEM);

    sin_table_kernel<<<(SEQ*DIM + 255)/256, 256>>>();
    embed_kernel<<<(NROW*DIM + 255)/256, 256>>>(x_tok, emb);
    {
        int total = 5*(QKV_W + PRJ_W + FF1_W + FF2_W);
        pack_all_kernel<<<(total + 255)/256, 256>>>(qkv_w, out_w, ff1_w, ff2_w);
    }

    for (int l = 0; l < 5; l++) {
        // QKV -> bf16 [.,900]
        mma_gemm_kernel<<<dim3(8, NROW/BM), 256, GEMM_SMEM>>>(p_hb,
            p_wqkv + (size_t)l*QKV_W, qkv_b + l*900, p_qkvb,
            900, 320, LDH, 1024, 900, 0, 1);
        attn_kernel<<<dim3(4, BATCH*NHEAD), 256, ATTN_SMEM>>>(p_qkvb, p_mask, p_att);
        // proj -> fp32
        mma_gemm_kernel<<<dim3(3, NROW/BM), 256, GEMM_SMEM>>>(p_att,
            p_wprj + (size_t)l*PRJ_W, out_b + l*DIM, p_prj,
            300, 320, LDH, 384, LDH, 0, 0);
        ln_kernel<<<NROW/8, 256>>>(p_h, p_prj, ln1_s + l*DIM, ln1_b + l*DIM,
                                   p_h1, p_h1b, nullptr);
        // FF1 + gelu -> bf16 [.,608]
        mma_gemm_kernel<<<dim3(5, NROW/BM), 256, GEMM_SMEM>>>(p_h1b,
            p_wff1 + (size_t)l*FF1_W, ff1_b + l*2*DIM, p_ff1,
            600, 320, LDH, 640, LDF, 1, 1);
        // FF2 -> fp32
        mma_gemm_kernel<<<dim3(3, NROW/BM), 256, GEMM_SMEM>>>(p_ff1,
            p_wff2 + (size_t)l*FF2_W, ff2_b + l*DIM, p_ff2,
            300, 608, LDF, 384, LDH, 0, 0);
        ln_kernel<<<NROW/8, 256>>>(p_h1, p_ff2, ln2_s + l*DIM, ln2_b + l*DIM,
                                   p_h, p_hb, p_mask);
    }

    rowdot_kernel<<<NROW/8, 256>>>(lin1_w, lin1_b);
    head_kernel<<<BATCH, 64>>>(lin2_w, lin2_b, lout_w, lout_b, laux_w, laux_b,
                               (float*)d_out);
}

// round 13
// speedup vs baseline: 1.2845x; 1.2845x over previous
#include <cuda_runtime.h>
#include <cuda_bf16.h>
#include <math.h>
#include <stdint.h>

// Problem constants
#define BATCH 256
#define SEQ   200
#define DIM   300
#define NHEAD 6
#define DHEAD 50
#define NROW  (BATCH*SEQ)        // 51200
#define LDH   320
#define LDF   608
#define GELU_C 0.7978845608028654f

// ---------------- scratch (device globals; zero-initialized) ------------------
__device__ float g_sin[SEQ*DIM];
__device__ float g_h  [NROW*LDH];
__device__ float g_h1 [NROW*LDH];
__device__ float g_prj[NROW*LDH];
__device__ float g_ff2[NROW*LDH];
__device__ float g_s1 [NROW];
__device__ unsigned char g_mask[NROW];

__device__ __nv_bfloat16 g_qkvb[NROW*900];
__device__ __nv_bfloat16 g_hb [NROW*LDH];
__device__ __nv_bfloat16 g_h1b[NROW*LDH];
__device__ __nv_bfloat16 g_att[NROW*LDH];
__device__ __nv_bfloat16 g_ff1[NROW*LDF];

// packed bf16 weights
#define QKV_W (160*1024)
#define PRJ_W (160*384)
#define FF1_W (160*640)
#define FF2_W (304*384)
__device__ uint32_t g_pw_qkv[5*QKV_W];
__device__ uint32_t g_pw_prj[5*PRJ_W];
__device__ uint32_t g_pw_ff1[5*FF1_W];
__device__ uint32_t g_pw_ff2[5*FF2_W];

__device__ __forceinline__ float gelu_f(float x) {
    float x3 = x*x*x;
    return 0.5f*x*(1.0f + tanhf(GELU_C*(x + 0.044715f*x3)));
}
__device__ __forceinline__ uint32_t smemu32(const void* p) {
    return (uint32_t)__cvta_generic_to_shared(p);
}
#define CP16(dst, src) asm volatile("cp.async.cg.shared.global [%0], [%1], 16;\n" :: "r"(dst), "l"(src))
#define CP_COMMIT()    asm volatile("cp.async.commit_group;\n" ::)
#define CP_WAIT(N)     asm volatile("cp.async.wait_group %0;\n" :: "n"(N))

#define MMA_BF16(acc, a0,a1,a2,a3, b0,b1) \
    asm volatile( \
        "mma.sync.aligned.m16n8k16.row.col.f32.bf16.bf16.f32 " \
        "{%0,%1,%2,%3}, {%4,%5,%6,%7}, {%8,%9}, {%0,%1,%2,%3};" \
        : "+f"((acc)[0]), "+f"((acc)[1]), "+f"((acc)[2]), "+f"((acc)[3]) \
        : "r"(a0), "r"(a1), "r"(a2), "r"(a3), "r"(b0), "r"(b1))

// ---------------- sinusoid table ----------------------------------------------
__global__ void sin_table_kernel() {
    int idx = blockIdx.x*blockDim.x + threadIdx.x;
    if (idx >= SEQ*DIM) return;
    int pos = idx / DIM, i = idx % DIM;
    double ang = (double)pos / pow(10000.0, 2.0*(double)(i/2)/(double)DIM);
    g_sin[idx] = (float)((i & 1) ? cos(ang) : sin(ang));
}

// ---------------- embedding + pos-enc + initial mask --------------------------
__global__ void embed_kernel(const int* __restrict__ tok,
                             const float* __restrict__ emb) {
    int idx = blockIdx.x*blockDim.x + threadIdx.x;
    if (idx >= NROW*DIM) return;
    int r = idx / DIM, d = idx % DIM;
    int t = tok[r];
    float v = emb[(size_t)t*DIM + d];
    if (t != 0) v += g_sin[(r % SEQ)*DIM + d];
    g_h [(size_t)r*LDH + d] = v;
    g_hb[(size_t)r*LDH + d] = __float2bfloat16_rn(v);
    if (d == 0) g_mask[r] = (t == 0) ? 1 : 0;
}

// ---------------- weight packing ----------------------------------------------
__device__ __forceinline__ void pack_bf(const float* __restrict__ src,
                                        uint32_t* __restrict__ dst, int i,
                                        int K, int N, int Kpw, int Np) {
    int per = Kpw*Np;
    int l = i / per, r = i % per;
    int kp = r / Np, n = r % Np;
    float f0 = (2*kp   < K && n < N) ? src[(size_t)l*K*N + (size_t)(2*kp  )*N + n] : 0.0f;
    float f1 = (2*kp+1 < K && n < N) ? src[(size_t)l*K*N + (size_t)(2*kp+1)*N + n] : 0.0f;
    __nv_bfloat162 p = __floats2bfloat162_rn(f0, f1);
    dst[i] = *reinterpret_cast<uint32_t*>(&p);
}
__global__ void pack_all_kernel(const float* __restrict__ qkv_w,
                                const float* __restrict__ out_w,
                                const float* __restrict__ ff1_w,
                                const float* __restrict__ ff2_w) {
    int i = blockIdx.x*blockDim.x + threadIdx.x;
    if (i < 5*QKV_W) { pack_bf(qkv_w, g_pw_qkv, i, 300, 900, 160, 1024); return; }
    i -= 5*QKV_W;
    if (i < 5*PRJ_W) { pack_bf(out_w, g_pw_prj, i, 300, 300, 160, 384); return; }
    i -= 5*PRJ_W;
    if (i < 5*FF1_W) { pack_bf(ff1_w, g_pw_ff1, i, 300, 600, 160, 640); return; }
    i -= 5*FF1_W;
    if (i < 5*FF2_W) { pack_bf(ff2_w, g_pw_ff2, i, 600, 300, 304, 384); return; }
}

// ---------------- BF16 tensor-core GEMM (5-stage, single-sync) ----------------
#define BM 128
#define BN 128
#define STAGES 5
#define ASTRIDE 20
#define BSTRIDE 136
#define A_ELEMS (BM*ASTRIDE)
#define B_ELEMS (16*BSTRIDE)
#define GEMM_SMEM ((STAGES*(A_ELEMS + B_ELEMS))*4)   // 94720 bytes

__global__ __launch_bounds__(256, 2) void mma_gemm_kernel(
        const __nv_bfloat16* __restrict__ A, const uint32_t* __restrict__ Bw,
        const float* __restrict__ bias, void* __restrict__ Cv,
        int N, int Kp, int lda, int Np, int ldc, int act, int obf) {
    extern __shared__ uint32_t dsm[];
    uint32_t* Asm = dsm;
    uint32_t* Bsm = dsm + STAGES*A_ELEMS;

    int tid = threadIdx.x;
    int warp = tid >> 5, lane = tid & 31;
    int g = lane >> 2, tig = lane & 3;
    int mw = (warp >> 2)*64, nw = (warp & 3)*32;
    int bm = blockIdx.y*BM, bn = blockIdx.x*BN;

    const __nv_bfloat16* Abase = A + (size_t)bm*lda;
    const uint32_t* Bbase = Bw + bn;

    float acc[4][4][4];
    #pragma unroll
    for (int i = 0; i < 4; i++)
        #pragma unroll
        for (int j = 0; j < 4; j++)
            #pragma unroll
            for (int r = 0; r < 4; r++) acc[i][j][r] = 0.0f;

    int nIter = Kp / 32;
    int am0 = tid >> 2,          awc0 = (tid & 3)*4;
    int am1 = (tid + 256) >> 2;
    int bk0 = tid >> 5,          bnc0 = (tid & 31)*4;
    int bk1 = (tid + 256) >> 5;

    auto loadStage = [&](int it, int s) {
        int k0e = it*32, k0w = it*16;
        uint32_t* As = Asm + s*A_ELEMS;
        uint32_t* Bs = Bsm + s*B_ELEMS;
        CP16(smemu32(&As[am0*ASTRIDE + awc0]), Abase + (size_t)am0*lda + k0e + awc0*2);
        CP16(smemu32(&As[am1*ASTRIDE + awc0]), Abase + (size_t)am1*lda + k0e + awc0*2);
        CP16(smemu32(&Bs[bk0*BSTRIDE + bnc0]), Bbase + (size_t)(k0w+bk0)*Np + bnc0);
        CP16(smemu32(&Bs[bk1*BSTRIDE + bnc0]), Bbase + (size_t)(k0w+bk1)*Np + bnc0);
    };

    #pragma unroll
    for (int s = 0; s < STAGES-1; s++) {
        loadStage(s, s);
        CP_COMMIT();
    }

    int cur = 0;
    for (int it = 0; it < nIter; it++) {
        CP_WAIT(STAGES-2);
        __syncthreads();

        const uint32_t* As = Asm + cur*A_ELEMS;
        const uint32_t* Bs = Bsm + cur*B_ELEMS;
        #pragma unroll
        for (int ks = 0; ks < 2; ks++) {
            int kb = ks*8;
            uint32_t af[4][4], bf[4][2];
            #pragma unroll
            for (int mt = 0; mt < 4; mt++) {
                int rm = mw + mt*16;
                af[mt][0] = As[(rm + g    )*ASTRIDE + kb + tig    ];
                af[mt][1] = As[(rm + g + 8)*ASTRIDE + kb + tig    ];
                af[mt][2] = As[(rm + g    )*ASTRIDE + kb + tig + 4];
                af[mt][3] = As[(rm + g + 8)*ASTRIDE + kb + tig + 4];
            }
            #pragma unroll
            for (int nt = 0; nt < 4; nt++) {
                int cn = nw + nt*8;
                bf[nt][0] = Bs[(kb + tig    )*BSTRIDE + cn + g];
                bf[nt][1] = Bs[(kb + tig + 4)*BSTRIDE + cn + g];
            }
            #pragma unroll
            for (int mt = 0; mt < 4; mt++)
                #pragma unroll
                for (int nt = 0; nt < 4; nt++)
                    MMA_BF16(acc[mt][nt], af[mt][0], af[mt][1], af[mt][2], af[mt][3],
                             bf[nt][0], bf[nt][1]);
        }

        if (it + STAGES-1 < nIter) {
            int s = (it + STAGES-1) % STAGES;
            loadStage(it + STAGES-1, s);
        }
        CP_COMMIT();
        cur = (cur + 1 == STAGES) ? 0 : cur + 1;
    }

    #pragma unroll
    for (int mt = 0; mt < 4; mt++) {
        int row0 = bm + mw + mt*16 + g;
        #pragma unroll
        for (int nt = 0; nt < 4; nt++) {
            int col = bn + nw + nt*8 + tig*2;
            if (col < N) {
                float b0 = bias[col], b1 = bias[col+1];
                float v0 = acc[mt][nt][0] + b0;
                float v1 = acc[mt][nt][1] + b1;
                float v2 = acc[mt][nt][2] + b0;
                float v3 = acc[mt][nt][3] + b1;
                if (act == 1) { v0 = gelu_f(v0); v1 = gelu_f(v1); v2 = gelu_f(v2); v3 = gelu_f(v3); }
                if (obf) {
                    __nv_bfloat16* C16 = (__nv_bfloat16*)Cv;
                    __nv_bfloat162 pa = __floats2bfloat162_rn(v0, v1);
                    __nv_bfloat162 pb = __floats2bfloat162_rn(v2, v3);
                    *(__nv_bfloat162*)&C16[(size_t)row0*ldc + col]     = pa;
                    *(__nv_bfloat162*)&C16[(size_t)(row0+8)*ldc + col] = pb;
                } else {
                    float* C = (float*)Cv;
                    *(float2*)&C[(size_t)row0*ldc + col]     = make_float2(v0, v1);
                    *(float2*)&C[(size_t)(row0+8)*ldc + col] = make_float2(v2, v3);
                }
            }
        }
    }
}

// ---------------- bf16 attention, R11 streaming structure ---------------------
// One block per (qchunk, b*h), 2 blocks/SM. K/V streamed as 64-key tiles
// through one shared word buffer. fp32 softmax (scale folded in).
#define AQS 36      // Qs[64 rows][36 dwords]     A-frag: 4g+tig conflict-free
#define TBS 72      // Tb[32 words][72]           B-frag: 8tig+g conflict-free
#define PSS 212     // Ps fp32 [64][212]
#define PBS 108     // Pb[64 rows][108 kwords]    A-frag: 12g+tig conflict-free
#define AQ_E (64*AQS)
#define TB_E (32*TBS)
#define PS_E (64*PSS)
#define PB_E (64*PBS)
#define ATTN_SMEM ((AQ_E + TB_E + PS_E + PB_E + 64)*4 + 256)

__global__ __launch_bounds__(256, 2) void attn_kernel(
        const __nv_bfloat16* __restrict__ qkv,
        const unsigned char* __restrict__ mask,
        __nv_bfloat16* __restrict__ out) {
    extern __shared__ uint32_t smw[];
    uint32_t* Qs = smw;
    uint32_t* Tb = Qs + AQ_E;
    float*    Ps = (float*)(Tb + TB_E);
    uint32_t* Pb = (uint32_t*)(Ps + PS_E);
    float*    inv = (float*)(Pb + PB_E);
    unsigned char* mk = (unsigned char*)(inv + 64);

    int bh = blockIdx.y;
    int b = bh / NHEAD, h = bh % NHEAD;
    int qbase = blockIdx.x * 64;
    int tid = threadIdx.x;
    int warp = tid >> 5, lane = tid & 31;
    int g = lane >> 2, tig = lane & 3;
    int wm = (warp >> 1)*16;
    int wn = warp & 1;

    const float scale = 0.1414213562373095f;  // 1/sqrt(50)
    const uint32_t* qw = (const uint32_t*)qkv;
    size_t rowbase = (size_t)b*SEQ*450;       // word offset of row 0

    if (tid < SEQ) mk[tid] = mask[b*SEQ + tid];
    int padcnt = __syncthreads_count(tid < SEQ && mask[b*SEQ + tid]);
    bool allpad = (padcnt == SEQ);

    // ---- fill Q chunk: 64 rows x 32 dwords (25 real) ----
    for (int i = tid; i < 64*32; i += 256) {
        int r = i >> 5, wc = i & 31;
        int q = qbase + r;
        uint32_t v = (wc < 25 && q < SEQ) ? qw[rowbase + (size_t)q*450 + h*25 + wc] : 0u;
        Qs[r*AQS + wc] = v;
    }
    __syncthreads();

    // ---- S = Q @ K^T, keys streamed in 4 tiles of 64 ----
    for (int kt = 0; kt < 4; kt++) {
        int K0 = kt*64;
        // fill K^T tile: Tb[dw][key] = word {K[key][2dw], K[key][2dw+1]}
        for (int i = tid; i < 2048; i += 256) {
            int dw = i & 31, key = i >> 5;
            uint32_t v = (dw < 25 && K0 + key < SEQ)
                       ? qw[rowbase + (size_t)(K0+key)*450 + 150 + h*25 + dw] : 0u;
            Tb[dw*TBS + key] = v;
        }
        __syncthreads();

        float sacc[4][4];
        #pragma unroll
        for (int nt = 0; nt < 4; nt++)
            #pragma unroll
            for (int r = 0; r < 4; r++) sacc[nt][r] = 0.0f;
        #pragma unroll
        for (int ks = 0; ks < 4; ks++) {
            int kb = ks*8;
            uint32_t a0 = Qs[(wm + g    )*AQS + kb + tig    ];
            uint32_t a1 = Qs[(wm + g + 8)*AQS + kb + tig    ];
            uint32_t a2 = Qs[(wm + g    )*AQS + kb + tig + 4];
            uint32_t a3 = Qs[(wm + g + 8)*AQS + kb + tig + 4];
            #pragma unroll
            for (int nt = 0; nt < 4; nt++) {
                int cn = wn*32 + nt*8;
                uint32_t b0 = Tb[(kb + tig    )*TBS + cn + g];
                uint32_t b1 = Tb[(kb + tig + 4)*TBS + cn + g];
                MMA_BF16(sacc[nt], a0, a1, a2, a3, b0, b1);
            }
        }
        #pragma unroll
        for (int nt = 0; nt < 4; nt++) {
            int col = K0 + wn*32 + nt*8 + tig*2;
            if (col < 208) {
                *(float2*)&Ps[(wm + g    )*PSS + col] = make_float2(sacc[nt][0], sacc[nt][1]);
                *(float2*)&Ps[(wm + g + 8)*PSS + col] = make_float2(sacc[nt][2], sacc[nt][3]);
            }
        }
        __syncthreads();
    }

    // ---- fp32 softmax (scale folded); pack P to bf16 key-pair words ----
    {
        int row = tid >> 2, j = tid & 3;
        int k0r = j*52;
        float m = -INFINITY;
        for (int k = k0r; k < k0r + 52; k++)
            if (k < SEQ && !mk[k]) m = fmaxf(m, Ps[row*PSS + k]*scale);
        m = fmaxf(m, __shfl_xor_sync(0xffffffffu, m, 1));
        m = fmaxf(m, __shfl_xor_sync(0xffffffffu, m, 2));
        float ssum = 0.0f;
        for (int kw = j*26; kw < j*26 + 26; kw++) {
            int ka = 2*kw, kb2 = 2*kw + 1;
            float p0 = 0.0f, p1 = 0.0f;
            if (ka  < SEQ && !mk[ka])  { p0 = __expf(Ps[row*PSS + ka ]*scale - m); ssum += p0; }
            if (kb2 < SEQ && !mk[kb2]) { p1 = __expf(Ps[row*PSS + kb2]*scale - m); ssum += p1; }
            __nv_bfloat162 pp = __floats2bfloat162_rn(p0, p1);
            Pb[row*PBS + kw] = *reinterpret_cast<uint32_t*>(&pp);
        }
        ssum += __shfl_xor_sync(0xffffffffu, ssum, 1);
        ssum += __shfl_xor_sync(0xffffffffu, ssum, 2);
        if (j == 0) inv[row] = (allpad || ssum == 0.0f) ? 0.0f : 1.0f/ssum;
    }
    __syncthreads();

    // ---- O = P @ V, keys streamed in 4 tiles (k-steps 4,4,4,1) ----
    float oacc[4][4];
    #pragma unroll
    for (int nt = 0; nt < 4; nt++)
        #pragma unroll
        for (int r = 0; r < 4; r++) oacc[nt][r] = 0.0f;

    for (int kt = 0; kt < 4; kt++) {
        int K0 = kt*64;       // key offset
        int K0w = kt*32;      // kword offset into Pb
        int nk = (kt == 3) ? 1 : 4;
        // fill V tile: Tb[kw][d] = word {V[K0+2kw][d], V[K0+2kw+1][d]}
        for (int i = tid; i < 2048; i += 256) {
            int d = i & 63, kw = i >> 6;
            uint32_t v = 0;
            if (d < DHEAD) {
                int k0 = K0 + 2*kw, k1 = K0 + 2*kw + 1;
                uint32_t lo = (k0 < SEQ) ? *(const uint16_t*)(qkv + (size_t)(b*SEQ + k0)*900 + 600 + h*DHEAD + d) : 0;
                uint32_t hi = (k1 < SEQ) ? *(const uint16_t*)(qkv + (size_t)(b*SEQ + k1)*900 + 600 + h*DHEAD + d) : 0;
                v = lo | (hi << 16);
            }
            Tb[kw*TBS + d] = v;
        }
        __syncthreads();

        for (int ks = 0; ks < nk; ks++) {
            int kb = ks*8;
            uint32_t a0 = Pb[(wm + g    )*PBS + K0w + kb + tig    ];
            uint32_t a1 = Pb[(wm + g + 8)*PBS + K0w + kb + tig    ];
            uint32_t a2 = Pb[(wm + g    )*PBS + K0w + kb + tig + 4];
            uint32_t a3 = Pb[(wm + g + 8)*PBS + K0w + kb + tig + 4];
            #pragma unroll
            for (int nt = 0; nt < 4; nt++) {
                int cn = wn*32 + nt*8;
                uint32_t b0 = Tb[(kb + tig    )*TBS + cn + g];
                uint32_t b1 = Tb[(kb + tig + 4)*TBS + cn + g];
                MMA_BF16(oacc[nt], a0, a1, a2, a3, b0, b1);
            }
        }
        __syncthreads();
    }

    // ---- epilogue: normalize + store bf16 ----
    {
        float v0 = inv[wm + g], v1 = inv[wm + g + 8];
        int q0 = qbase + wm + g;
        #pragma unroll
        for (int nt = 0; nt < 4; nt++) {
            int col = wn*32 + nt*8 + tig*2;
            if (col < DHEAD) {
                if (q0 < SEQ) {
                    __nv_bfloat162 p = __floats2bfloat162_rn(oacc[nt][0]*v0, oacc[nt][1]*v0);
                    *(__nv_bfloat162*)&out[(size_t)(b*SEQ + q0)*LDH + h*DHEAD + col] = p;
                }
                if (q0 + 8 < SEQ) {
                    __nv_bfloat162 p = __floats2bfloat162_rn(oacc[nt][2]*v1, oacc[nt][3]*v1);
                    *(__nv_bfloat162*)&out[(size_t)(b*SEQ + q0 + 8)*LDH + h*DHEAD + col] = p;
                }
            }
        }
    }
}

// ---------------- warp-per-row residual add + LayerNorm -----------------------
__global__ void ln_kernel(const float* __restrict__ X,
                          const float* __restrict__ Y,
                          const float* __restrict__ s,
                          const float* __restrict__ bcoef,
                          float* __restrict__ out,
                          __nv_bfloat16* __restrict__ outb,
                          unsigned char* maskout) {
    int tid = threadIdx.x, warp = tid >> 5, lane = tid & 31;
    int r = blockIdx.x*8 + warp;
    if (r >= NROW) return;

    float v[10]; int nd = 0;
    float sum = 0.0f;
    for (int d = lane; d < DIM; d += 32) {
        float t = X[(size_t)r*LDH + d] + Y[(size_t)r*LDH + d];
        v[nd++] = t;
        sum += t;
    }
    #pragma unroll
    for (int off = 16; off > 0; off >>= 1) sum += __shfl_xor_sync(0xffffffffu, sum, off);
    float mean = sum / (float)DIM;

    float var = 0.0f;
    for (int i = 0; i < nd; i++) { float d0 = v[i] - mean; var += d0*d0; }
    #pragma unroll
    for (int off = 16; off > 0; off >>= 1) var += __shfl_xor_sync(0xffffffffu, var, off);
    float rstd = 1.0f / sqrtf(var/(float)DIM + 1e-5f);

    bool allz = true;
    int i2 = 0;
    for (int d = lane; d < DIM; d += 32) {
        float o = (v[i2++] - mean)*rstd*s[d] + bcoef[d];
        out[(size_t)r*LDH + d] = o;
        outb[(size_t)r*LDH + d] = __float2bfloat16_rn(o);
        if (o != 0.0f) allz = false;
    }
    if (maskout) {
        bool all = __all_sync(0xffffffffu, allz);
        if (lane == 0) maskout[r] = all ? 1 : 0;
    }
}

// ---------------- head kernels ------------------------------------------------
__global__ void rowdot_kernel(const float* __restrict__ w1,
                              const float* __restrict__ b1) {
    int tid = threadIdx.x, warp = tid >> 5, lane = tid & 31;
    int r = blockIdx.x*8 + warp;
    if (r >= NROW) return;
    float acc = 0.0f;
    for (int d = lane; d < DIM; d += 32)
        acc += g_h[(size_t)r*LDH + d] * w1[d];
    #pragma unroll
    for (int off = 16; off > 0; off >>= 1) acc += __shfl_xor_sync(0xffffffffu, acc, off);
    if (lane == 0) g_s1[r] = acc + b1[0];
}

__global__ void head_kernel(const float* __restrict__ w2, const float* __restrict__ b2,
                            const float* __restrict__ wo, const float* __restrict__ bo,
                            const float* __restrict__ wa, const float* __restrict__ ba,
                            float* __restrict__ out) {
    __shared__ float s1s[SEQ];
    __shared__ float s2s[50];
    int b = blockIdx.x, tid = threadIdx.x;
    for (int i = tid; i < SEQ; i += 64) s1s[i] = g_s1[b*SEQ + i];
    __syncthreads();
    if (tid < 50) {
        float acc = 0.0f;
        for (int s = 0; s < SEQ; s++) acc += s1s[s]*w2[s*50 + tid];
        s2s[tid] = gelu_f(acc + b2[tid]);
    }
    __syncthreads();
    if (tid < 7) {
        float acc = 0.0f;
        if (tid == 0) {
            for (int i = 0; i < 50; i++) acc += s2s[i]*wo[i];
            out[b*7] = acc + bo[0];
        } else {
            int j = tid - 1;
            for (int i = 0; i < 50; i++) acc += s2s[i]*wa[i*6 + j];
            out[b*7 + tid] = acc + ba[j];
        }
    }
}

// ---------------- launch ------------------------------------------------------
extern "C" void kernel_launch(void* const* d_in, const int* in_sizes, int n_in,
                              void* d_out, int out_size) {
    const int*   x_tok  = (const int*)  d_in[0];
    const float* emb    = (const float*)d_in[1];
    const float* qkv_w  = (const float*)d_in[2];
    const float* qkv_b  = (const float*)d_in[3];
    const float* out_w  = (const float*)d_in[4];
    const float* out_b  = (const float*)d_in[5];
    const float* ln1_s  = (const float*)d_in[6];
    const float* ln1_b  = (const float*)d_in[7];
    const float* ff1_w  = (const float*)d_in[8];
    const float* ff1_b  = (const float*)d_in[9];
    const float* ff2_w  = (const float*)d_in[10];
    const float* ff2_b  = (const float*)d_in[11];
    const float* ln2_s  = (const float*)d_in[12];
    const float* ln2_b  = (const float*)d_in[13];
    const float* lin1_w = (const float*)d_in[14];
    const float* lin1_b = (const float*)d_in[15];
    const float* lin2_w = (const float*)d_in[16];
    const float* lin2_b = (const float*)d_in[17];
    const float* lout_w = (const float*)d_in[18];
    const float* lout_b = (const float*)d_in[19];
    const float* laux_w = (const float*)d_in[20];
    const float* laux_b = (const float*)d_in[21];

    float *p_h, *p_h1, *p_prj, *p_ff2;
    __nv_bfloat16 *p_qkvb, *p_hb, *p_h1b, *p_att, *p_ff1;
    uint32_t *p_wqkv, *p_wprj, *p_wff1, *p_wff2;
    unsigned char *p_mask;
    cudaGetSymbolAddress((void**)&p_h,    g_h);
    cudaGetSymbolAddress((void**)&p_h1,   g_h1);
    cudaGetSymbolAddress((void**)&p_prj,  g_prj);
    cudaGetSymbolAddress((void**)&p_ff2,  g_ff2);
    cudaGetSymbolAddress((void**)&p_qkvb, g_qkvb);
    cudaGetSymbolAddress((void**)&p_hb,   g_hb);
    cudaGetSymbolAddress((void**)&p_h1b,  g_h1b);
    cudaGetSymbolAddress((void**)&p_att,  g_att);
    cudaGetSymbolAddress((void**)&p_ff1,  g_ff1);
    cudaGetSymbolAddress((void**)&p_mask, g_mask);
    cudaGetSymbolAddress((void**)&p_wqkv, g_pw_qkv);
    cudaGetSymbolAddress((void**)&p_wprj, g_pw_prj);
    cudaGetSymbolAddress((void**)&p_wff1, g_pw_ff1);
    cudaGetSymbolAddress((void**)&p_wff2, g_pw_ff2);

    cudaFuncSetAttribute(attn_kernel, cudaFuncAttributeMaxDynamicSharedMemorySize,
                         ATTN_SMEM);
    cudaFuncSetAttribute(mma_gemm_kernel, cudaFuncAttributeMaxDynamicSharedMemorySize,
                         GEMM_SMEM);

    sin_table_kernel<<<(SEQ*DIM + 255)/256, 256>>>();
    embed_kernel<<<(NROW*DIM + 255)/256, 256>>>(x_tok, emb);
    {
        int total = 5*(QKV_W + PRJ_W + FF1_W + FF2_W);
        pack_all_kernel<<<(total + 255)/256, 256>>>(qkv_w, out_w, ff1_w, ff2_w);
    }

    for (int l = 0; l < 5; l++) {
        // QKV -> bf16 [.,900]
        mma_gemm_kernel<<<dim3(8, NROW/BM), 256, GEMM_SMEM>>>(p_hb,
            p_wqkv + (size_t)l*QKV_W, qkv_b + l*900, p_qkvb,
            900, 320, LDH, 1024, 900, 0, 1);
        attn_kernel<<<dim3(4, BATCH*NHEAD), 256, ATTN_SMEM>>>(p_qkvb, p_mask, p_att);
        // proj -> fp32
        mma_gemm_kernel<<<dim3(3, NROW/BM), 256, GEMM_SMEM>>>(p_att,
            p_wprj + (size_t)l*PRJ_W, out_b + l*DIM, p_prj,
            300, 320, LDH, 384, LDH, 0, 0);
        ln_kernel<<<NROW/8, 256>>>(p_h, p_prj, ln1_s + l*DIM, ln1_b + l*DIM,
                                   p_h1, p_h1b, nullptr);
        // FF1 + gelu -> bf16 [.,608]
        mma_gemm_kernel<<<dim3(5, NROW/BM), 256, GEMM_SMEM>>>(p_h1b,
            p_wff1 + (size_t)l*FF1_W, ff1_b + l*2*DIM, p_ff1,
            600, 320, LDH, 640, LDF, 1, 1);
        // FF2 -> fp32
        mma_gemm_kernel<<<dim3(3, NROW/BM), 256, GEMM_SMEM>>>(p_ff1,
            p_wff2 + (size_t)l*FF2_W, ff2_b + l*DIM, p_ff2,
            300, 608, LDF, 384, LDH, 0, 0);
        ln_kernel<<<NROW/8, 256>>>(p_h1, p_ff2, ln2_s + l*DIM, ln2_b + l*DIM,
                                   p_h, p_hb, p_mask);
    }

    rowdot_kernel<<<NROW/8, 256>>>(lin1_w, lin1_b);
    head_kernel<<<BATCH, 64>>>(lin2_w, lin2_b, lout_w, lout_b, laux_w, laux_b,
                               (float*)d_out);
}

// round 14
// speedup vs baseline: 1.4032x; 1.0924x over previous
#include <cuda_runtime.h>
#include <cuda_bf16.h>
#include <math.h>
#include <stdint.h>

// Problem constants
#define BATCH 256
#define SEQ   200
#define DIM   300
#define NHEAD 6
#define DHEAD 50
#define NROW  (BATCH*SEQ)        // 51200
#define LDH   320
#define LDF   608
#define GELU_C 0.7978845608028654f

// ---------------- scratch (device globals; zero-initialized) ------------------
__device__ float g_sin[SEQ*DIM];
__device__ float g_h  [NROW*LDH];
__device__ float g_h1 [NROW*LDH];
__device__ float g_prj[NROW*LDH];
__device__ float g_ff2[NROW*LDH];
__device__ float g_s1 [NROW];
__device__ unsigned char g_mask[NROW];

__device__ __nv_bfloat16 g_qkvb[NROW*900];
__device__ __nv_bfloat16 g_hb [NROW*LDH];
__device__ __nv_bfloat16 g_h1b[NROW*LDH];
__device__ __nv_bfloat16 g_att[NROW*LDH];
__device__ __nv_bfloat16 g_ff1[NROW*LDF];

// packed bf16 weights
#define QKV_W (160*1024)
#define PRJ_W (160*384)
#define FF1_W (160*640)
#define FF2_W (304*384)
__device__ uint32_t g_pw_qkv[5*QKV_W];
__device__ uint32_t g_pw_prj[5*PRJ_W];
__device__ uint32_t g_pw_ff1[5*FF1_W];
__device__ uint32_t g_pw_ff2[5*FF2_W];

__device__ __forceinline__ float gelu_f(float x) {
    float x3 = x*x*x;
    return 0.5f*x*(1.0f + tanhf(GELU_C*(x + 0.044715f*x3)));
}
__device__ __forceinline__ uint32_t smemu32(const void* p) {
    return (uint32_t)__cvta_generic_to_shared(p);
}
#define CP16(dst, src) asm volatile("cp.async.cg.shared.global [%0], [%1], 16;\n" :: "r"(dst), "l"(src))
#define CP_COMMIT()    asm volatile("cp.async.commit_group;\n" ::)
#define CP_WAIT(N)     asm volatile("cp.async.wait_group %0;\n" :: "n"(N))

#define MMA_BF16(acc, a0,a1,a2,a3, b0,b1) \
    asm volatile( \
        "mma.sync.aligned.m16n8k16.row.col.f32.bf16.bf16.f32 " \
        "{%0,%1,%2,%3}, {%4,%5,%6,%7}, {%8,%9}, {%0,%1,%2,%3};" \
        : "+f"((acc)[0]), "+f"((acc)[1]), "+f"((acc)[2]), "+f"((acc)[3]) \
        : "r"(a0), "r"(a1), "r"(a2), "r"(a3), "r"(b0), "r"(b1))

// ---------------- sinusoid table ----------------------------------------------
__global__ void sin_table_kernel() {
    int idx = blockIdx.x*blockDim.x + threadIdx.x;
    if (idx >= SEQ*DIM) return;
    int pos = idx / DIM, i = idx % DIM;
    double ang = (double)pos / pow(10000.0, 2.0*(double)(i/2)/(double)DIM);
    g_sin[idx] = (float)((i & 1) ? cos(ang) : sin(ang));
}

// ---------------- embedding + pos-enc + initial mask --------------------------
__global__ void embed_kernel(const int* __restrict__ tok,
                             const float* __restrict__ emb) {
    int idx = blockIdx.x*blockDim.x + threadIdx.x;
    if (idx >= NROW*DIM) return;
    int r = idx / DIM, d = idx % DIM;
    int t = tok[r];
    float v = emb[(size_t)t*DIM + d];
    if (t != 0) v += g_sin[(r % SEQ)*DIM + d];
    g_h [(size_t)r*LDH + d] = v;
    g_hb[(size_t)r*LDH + d] = __float2bfloat16_rn(v);
    if (d == 0) g_mask[r] = (t == 0) ? 1 : 0;
}

// ---------------- weight packing ----------------------------------------------
__device__ __forceinline__ void pack_bf(const float* __restrict__ src,
                                        uint32_t* __restrict__ dst, int i,
                                        int K, int N, int Kpw, int Np) {
    int per = Kpw*Np;
    int l = i / per, r = i % per;
    int kp = r / Np, n = r % Np;
    float f0 = (2*kp   < K && n < N) ? src[(size_t)l*K*N + (size_t)(2*kp  )*N + n] : 0.0f;
    float f1 = (2*kp+1 < K && n < N) ? src[(size_t)l*K*N + (size_t)(2*kp+1)*N + n] : 0.0f;
    __nv_bfloat162 p = __floats2bfloat162_rn(f0, f1);
    dst[i] = *reinterpret_cast<uint32_t*>(&p);
}
__global__ void pack_all_kernel(const float* __restrict__ qkv_w,
                                const float* __restrict__ out_w,
                                const float* __restrict__ ff1_w,
                                const float* __restrict__ ff2_w) {
    int i = blockIdx.x*blockDim.x + threadIdx.x;
    if (i < 5*QKV_W) { pack_bf(qkv_w, g_pw_qkv, i, 300, 900, 160, 1024); return; }
    i -= 5*QKV_W;
    if (i < 5*PRJ_W) { pack_bf(out_w, g_pw_prj, i, 300, 300, 160, 384); return; }
    i -= 5*PRJ_W;
    if (i < 5*FF1_W) { pack_bf(ff1_w, g_pw_ff1, i, 300, 600, 160, 640); return; }
    i -= 5*FF1_W;
    if (i < 5*FF2_W) { pack_bf(ff2_w, g_pw_ff2, i, 600, 300, 304, 384); return; }
}

// ---------------- BF16 tensor-core GEMM (5-stage, single-sync) ----------------
#define BM 128
#define BN 128
#define STAGES 5
#define ASTRIDE 20
#define BSTRIDE 136
#define A_ELEMS (BM*ASTRIDE)
#define B_ELEMS (16*BSTRIDE)
#define GEMM_SMEM ((STAGES*(A_ELEMS + B_ELEMS))*4)   // 94720 bytes

__global__ __launch_bounds__(256, 2) void mma_gemm_kernel(
        const __nv_bfloat16* __restrict__ A, const uint32_t* __restrict__ Bw,
        const float* __restrict__ bias, void* __restrict__ Cv,
        int N, int Kp, int lda, int Np, int ldc, int act, int obf) {
    extern __shared__ uint32_t dsm[];
    uint32_t* Asm = dsm;
    uint32_t* Bsm = dsm + STAGES*A_ELEMS;

    int tid = threadIdx.x;
    int warp = tid >> 5, lane = tid & 31;
    int g = lane >> 2, tig = lane & 3;
    int mw = (warp >> 2)*64, nw = (warp & 3)*32;
    int bm = blockIdx.y*BM, bn = blockIdx.x*BN;

    const __nv_bfloat16* Abase = A + (size_t)bm*lda;
    const uint32_t* Bbase = Bw + bn;

    float acc[4][4][4];
    #pragma unroll
    for (int i = 0; i < 4; i++)
        #pragma unroll
        for (int j = 0; j < 4; j++)
            #pragma unroll
            for (int r = 0; r < 4; r++) acc[i][j][r] = 0.0f;

    int nIter = Kp / 32;
    int am0 = tid >> 2,          awc0 = (tid & 3)*4;
    int am1 = (tid + 256) >> 2;
    int bk0 = tid >> 5,          bnc0 = (tid & 31)*4;
    int bk1 = (tid + 256) >> 5;

    auto loadStage = [&](int it, int s) {
        int k0e = it*32, k0w = it*16;
        uint32_t* As = Asm + s*A_ELEMS;
        uint32_t* Bs = Bsm + s*B_ELEMS;
        CP16(smemu32(&As[am0*ASTRIDE + awc0]), Abase + (size_t)am0*lda + k0e + awc0*2);
        CP16(smemu32(&As[am1*ASTRIDE + awc0]), Abase + (size_t)am1*lda + k0e + awc0*2);
        CP16(smemu32(&Bs[bk0*BSTRIDE + bnc0]), Bbase + (size_t)(k0w+bk0)*Np + bnc0);
        CP16(smemu32(&Bs[bk1*BSTRIDE + bnc0]), Bbase + (size_t)(k0w+bk1)*Np + bnc0);
    };

    #pragma unroll
    for (int s = 0; s < STAGES-1; s++) {
        loadStage(s, s);
        CP_COMMIT();
    }

    int cur = 0;
    for (int it = 0; it < nIter; it++) {
        CP_WAIT(STAGES-2);
        __syncthreads();

        const uint32_t* As = Asm + cur*A_ELEMS;
        const uint32_t* Bs = Bsm + cur*B_ELEMS;
        #pragma unroll
        for (int ks = 0; ks < 2; ks++) {
            int kb = ks*8;
            uint32_t af[4][4], bf[4][2];
            #pragma unroll
            for (int mt = 0; mt < 4; mt++) {
                int rm = mw + mt*16;
                af[mt][0] = As[(rm + g    )*ASTRIDE + kb + tig    ];
                af[mt][1] = As[(rm + g + 8)*ASTRIDE + kb + tig    ];
                af[mt][2] = As[(rm + g    )*ASTRIDE + kb + tig + 4];
                af[mt][3] = As[(rm + g + 8)*ASTRIDE + kb + tig + 4];
            }
            #pragma unroll
            for (int nt = 0; nt < 4; nt++) {
                int cn = nw + nt*8;
                bf[nt][0] = Bs[(kb + tig    )*BSTRIDE + cn + g];
                bf[nt][1] = Bs[(kb + tig + 4)*BSTRIDE + cn + g];
            }
            #pragma unroll
            for (int mt = 0; mt < 4; mt++)
                #pragma unroll
                for (int nt = 0; nt < 4; nt++)
                    MMA_BF16(acc[mt][nt], af[mt][0], af[mt][1], af[mt][2], af[mt][3],
                             bf[nt][0], bf[nt][1]);
        }

        if (it + STAGES-1 < nIter) {
            int s = (it + STAGES-1) % STAGES;
            loadStage(it + STAGES-1, s);
        }
        CP_COMMIT();
        cur = (cur + 1 == STAGES) ? 0 : cur + 1;
    }

    #pragma unroll
    for (int mt = 0; mt < 4; mt++) {
        int row0 = bm + mw + mt*16 + g;
        #pragma unroll
        for (int nt = 0; nt < 4; nt++) {
            int col = bn + nw + nt*8 + tig*2;
            if (col < N) {
                float b0 = bias[col], b1 = bias[col+1];
                float v0 = acc[mt][nt][0] + b0;
                float v1 = acc[mt][nt][1] + b1;
                float v2 = acc[mt][nt][2] + b0;
                float v3 = acc[mt][nt][3] + b1;
                if (act == 1) { v0 = gelu_f(v0); v1 = gelu_f(v1); v2 = gelu_f(v2); v3 = gelu_f(v3); }
                if (obf) {
                    __nv_bfloat16* C16 = (__nv_bfloat16*)Cv;
                    __nv_bfloat162 pa = __floats2bfloat162_rn(v0, v1);
                    __nv_bfloat162 pb = __floats2bfloat162_rn(v2, v3);
                    *(__nv_bfloat162*)&C16[(size_t)row0*ldc + col]     = pa;
                    *(__nv_bfloat162*)&C16[(size_t)(row0+8)*ldc + col] = pb;
                } else {
                    float* C = (float*)Cv;
                    *(float2*)&C[(size_t)row0*ldc + col]     = make_float2(v0, v1);
                    *(float2*)&C[(size_t)(row0+8)*ldc + col] = make_float2(v2, v3);
                }
            }
        }
    }
}

// ---------------- bf16 attention, register-staged tile prefetch ---------------
// Same R13 structure (streamed 64-key tiles, 2 blocks/SM); each thread stages
// its 8 tile words for tile kt+1 in registers while tile kt's MMAs run.
#define AQS 36
#define TBS 72
#define PSS 212
#define PBS 108
#define AQ_E (64*AQS)
#define TB_E (32*TBS)
#define PS_E (64*PSS)
#define PB_E (64*PBS)
#define ATTN_SMEM ((AQ_E + TB_E + PS_E + PB_E + 64)*4 + 256)

__global__ __launch_bounds__(256, 2) void attn_kernel(
        const __nv_bfloat16* __restrict__ qkv,
        const unsigned char* __restrict__ mask,
        __nv_bfloat16* __restrict__ out) {
    extern __shared__ uint32_t smw[];
    uint32_t* Qs = smw;
    uint32_t* Tb = Qs + AQ_E;
    float*    Ps = (float*)(Tb + TB_E);
    uint32_t* Pb = (uint32_t*)(Ps + PS_E);
    float*    inv = (float*)(Pb + PB_E);
    unsigned char* mk = (unsigned char*)(inv + 64);

    int bh = blockIdx.y;
    int b = bh / NHEAD, h = bh % NHEAD;
    int qbase = blockIdx.x * 64;
    int tid = threadIdx.x;
    int warp = tid >> 5, lane = tid & 31;
    int g = lane >> 2, tig = lane & 3;
    int wm = (warp >> 1)*16;
    int wn = warp & 1;

    const float scale = 0.1414213562373095f;  // 1/sqrt(50)
    const uint32_t* qw = (const uint32_t*)qkv;
    size_t rowbase = (size_t)b*SEQ*450;

    // per-thread tile-entry coords (8 entries each)
    int kdw  = tid & 31, kkey0 = tid >> 5;      // K: dw fixed, key = kkey0 + j*8
    int vd   = tid & 63, vkw0  = tid >> 6;      // V: d fixed,  kw  = vkw0 + j*4

    uint32_t pre[8];

    auto loadK = [&](int kt) {
        int K0 = kt*64;
        #pragma unroll
        for (int j = 0; j < 8; j++) {
            int key = kkey0 + j*8;
            pre[j] = (kdw < 25 && K0 + key < SEQ)
                   ? qw[rowbase + (size_t)(K0+key)*450 + 150 + h*25 + kdw] : 0u;
        }
    };
    auto storeK = [&]() {
        #pragma unroll
        for (int j = 0; j < 8; j++)
            Tb[kdw*TBS + kkey0 + j*8] = pre[j];
    };
    auto loadV = [&](int kt) {
        int K0 = kt*64;
        #pragma unroll
        for (int j = 0; j < 8; j++) {
            int kw = vkw0 + j*4;
            uint32_t v = 0;
            if (vd < DHEAD) {
                int k0 = K0 + 2*kw, k1 = K0 + 2*kw + 1;
                uint32_t lo = (k0 < SEQ) ? *(const uint16_t*)(qkv + (size_t)(b*SEQ + k0)*900 + 600 + h*DHEAD + vd) : 0;
                uint32_t hi = (k1 < SEQ) ? *(const uint16_t*)(qkv + (size_t)(b*SEQ + k1)*900 + 600 + h*DHEAD + vd) : 0;
                v = lo | (hi << 16);
            }
            pre[j] = v;
        }
    };
    auto storeV = [&]() {
        #pragma unroll
        for (int j = 0; j < 8; j++)
            Tb[(vkw0 + j*4)*TBS + vd] = pre[j];
    };

    if (tid < SEQ) mk[tid] = mask[b*SEQ + tid];
    int padcnt = __syncthreads_count(tid < SEQ && mask[b*SEQ + tid]);
    bool allpad = (padcnt == SEQ);

    // fill Q chunk + prefetch K tile 0
    loadK(0);
    for (int i = tid; i < 64*32; i += 256) {
        int r = i >> 5, wc = i & 31;
        int q = qbase + r;
        uint32_t v = (wc < 25 && q < SEQ) ? qw[rowbase + (size_t)q*450 + h*25 + wc] : 0u;
        Qs[r*AQS + wc] = v;
    }

    // ---- S = Q @ K^T, keys streamed in 4 tiles of 64 ----
    for (int kt = 0; kt < 4; kt++) {
        __syncthreads();              // Tb free (prev tile MMAs done) + Q ready on kt=0
        storeK();
        __syncthreads();              // Tb ready
        if (kt < 3) loadK(kt + 1);    // overlap next tile loads with MMAs
        else        loadV(0);         // overlap V tile 0 gather with last S MMAs + softmax

        float sacc[4][4];
        #pragma unroll
        for (int nt = 0; nt < 4; nt++)
            #pragma unroll
            for (int r = 0; r < 4; r++) sacc[nt][r] = 0.0f;
        #pragma unroll
        for (int ks = 0; ks < 4; ks++) {
            int kb = ks*8;
            uint32_t a0 = Qs[(wm + g    )*AQS + kb + tig    ];
            uint32_t a1 = Qs[(wm + g + 8)*AQS + kb + tig    ];
            uint32_t a2 = Qs[(wm + g    )*AQS + kb + tig + 4];
            uint32_t a3 = Qs[(wm + g + 8)*AQS + kb + tig + 4];
            #pragma unroll
            for (int nt = 0; nt < 4; nt++) {
                int cn = wn*32 + nt*8;
                uint32_t b0 = Tb[(kb + tig    )*TBS + cn + g];
                uint32_t b1 = Tb[(kb + tig + 4)*TBS + cn + g];
                MMA_BF16(sacc[nt], a0, a1, a2, a3, b0, b1);
            }
        }
        int K0 = kt*64;
        #pragma unroll
        for (int nt = 0; nt < 4; nt++) {
            int col = K0 + wn*32 + nt*8 + tig*2;
            if (col < 208) {
                *(float2*)&Ps[(wm + g    )*PSS + col] = make_float2(sacc[nt][0], sacc[nt][1]);
                *(float2*)&Ps[(wm + g + 8)*PSS + col] = make_float2(sacc[nt][2], sacc[nt][3]);
            }
        }
    }
    __syncthreads();                  // Ps complete (also: last S MMAs done with Tb)

    // ---- fp32 softmax (scale folded); pack P to bf16 key-pair words ----
    {
        int row = tid >> 2, j = tid & 3;
        int k0r = j*52;
        float m = -INFINITY;
        for (int k = k0r; k < k0r + 52; k++)
            if (k < SEQ && !mk[k]) m = fmaxf(m, Ps[row*PSS + k]*scale);
        m = fmaxf(m, __shfl_xor_sync(0xffffffffu, m, 1));
        m = fmaxf(m, __shfl_xor_sync(0xffffffffu, m, 2));
        float ssum = 0.0f;
        for (int kw = j*26; kw < j*26 + 26; kw++) {
            int ka = 2*kw, kb2 = 2*kw + 1;
            float p0 = 0.0f, p1 = 0.0f;
            if (ka  < SEQ && !mk[ka])  { p0 = __expf(Ps[row*PSS + ka ]*scale - m); ssum += p0; }
            if (kb2 < SEQ && !mk[kb2]) { p1 = __expf(Ps[row*PSS + kb2]*scale - m); ssum += p1; }
            __nv_bfloat162 pp = __floats2bfloat162_rn(p0, p1);
            Pb[row*PBS + kw] = *reinterpret_cast<uint32_t*>(&pp);
        }
        ssum += __shfl_xor_sync(0xffffffffu, ssum, 1);
        ssum += __shfl_xor_sync(0xffffffffu, ssum, 2);
        if (j == 0) inv[row] = (allpad || ssum == 0.0f) ? 0.0f : 1.0f/ssum;
    }

    // ---- O = P @ V, keys streamed in 4 tiles (k-steps 4,4,4,1) ----
    float oacc[4][4];
    #pragma unroll
    for (int nt = 0; nt < 4; nt++)
        #pragma unroll
        for (int r = 0; r < 4; r++) oacc[nt][r] = 0.0f;

    for (int kt = 0; kt < 4; kt++) {
        __syncthreads();              // Pb complete (kt=0) / Tb free (kt>0)
        storeV();
        __syncthreads();
        if (kt < 3) loadV(kt + 1);

        int K0w = kt*32;
        int nk = (kt == 3) ? 1 : 4;
        for (int ks = 0; ks < nk; ks++) {
            int kb = ks*8;
            uint32_t a0 = Pb[(wm + g    )*PBS + K0w + kb + tig    ];
            uint32_t a1 = Pb[(wm + g + 8)*PBS + K0w + kb + tig    ];
            uint32_t a2 = Pb[(wm + g    )*PBS + K0w + kb + tig + 4];
            uint32_t a3 = Pb[(wm + g + 8)*PBS + K0w + kb + tig + 4];
            #pragma unroll
            for (int nt = 0; nt < 4; nt++) {
                int cn = wn*32 + nt*8;
                uint32_t b0 = Tb[(kb + tig    )*TBS + cn + g];
                uint32_t b1 = Tb[(kb + tig + 4)*TBS + cn + g];
                MMA_BF16(oacc[nt], a0, a1, a2, a3, b0, b1);
            }
        }
    }

    // ---- epilogue: normalize + store bf16 ----
    {
        float v0 = inv[wm + g], v1 = inv[wm + g + 8];
        int q0 = qbase + wm + g;
        #pragma unroll
        for (int nt = 0; nt < 4; nt++) {
            int col = wn*32 + nt*8 + tig*2;
            if (col < DHEAD) {
                if (q0 < SEQ) {
                    __nv_bfloat162 p = __floats2bfloat162_rn(oacc[nt][0]*v0, oacc[nt][1]*v0);
                    *(__nv_bfloat162*)&out[(size_t)(b*SEQ + q0)*LDH + h*DHEAD + col] = p;
                }
                if (q0 + 8 < SEQ) {
                    __nv_bfloat162 p = __floats2bfloat162_rn(oacc[nt][2]*v1, oacc[nt][3]*v1);
                    *(__nv_bfloat162*)&out[(size_t)(b*SEQ + q0 + 8)*LDH + h*DHEAD + col] = p;
                }
            }
        }
    }
}

// ---------------- warp-per-row residual add + LayerNorm -----------------------
__global__ void ln_kernel(const float* __restrict__ X,
                          const float* __restrict__ Y,
                          const float* __restrict__ s,
                          const float* __restrict__ bcoef,
                          float* __restrict__ out,
                          __nv_bfloat16* __restrict__ outb,
                          unsigned char* maskout) {
    int tid = threadIdx.x, warp = tid >> 5, lane = tid & 31;
    int r = blockIdx.x*8 + warp;
    if (r >= NROW) return;

    float v[10]; int nd = 0;
    float sum = 0.0f;
    for (int d = lane; d < DIM; d += 32) {
        float t = X[(size_t)r*LDH + d] + Y[(size_t)r*LDH + d];
        v[nd++] = t;
        sum += t;
    }
    #pragma unroll
    for (int off = 16; off > 0; off >>= 1) sum += __shfl_xor_sync(0xffffffffu, sum, off);
    float mean = sum / (float)DIM;

    float var = 0.0f;
    for (int i = 0; i < nd; i++) { float d0 = v[i] - mean; var += d0*d0; }
    #pragma unroll
    for (int off = 16; off > 0; off >>= 1) var += __shfl_xor_sync(0xffffffffu, var, off);
    float rstd = 1.0f / sqrtf(var/(float)DIM + 1e-5f);

    bool allz = true;
    int i2 = 0;
    for (int d = lane; d < DIM; d += 32) {
        float o = (v[i2++] - mean)*rstd*s[d] + bcoef[d];
        out[(size_t)r*LDH + d] = o;
        outb[(size_t)r*LDH + d] = __float2bfloat16_rn(o);
        if (o != 0.0f) allz = false;
    }
    if (maskout) {
        bool all = __all_sync(0xffffffffu, allz);
        if (lane == 0) maskout[r] = all ? 1 : 0;
    }
}

// ---------------- head kernels ------------------------------------------------
__global__ void rowdot_kernel(const float* __restrict__ w1,
                              const float* __restrict__ b1) {
    int tid = threadIdx.x, warp = tid >> 5, lane = tid & 31;
    int r = blockIdx.x*8 + warp;
    if (r >= NROW) return;
    float acc = 0.0f;
    for (int d = lane; d < DIM; d += 32)
        acc += g_h[(size_t)r*LDH + d] * w1[d];
    #pragma unroll
    for (int off = 16; off > 0; off >>= 1) acc += __shfl_xor_sync(0xffffffffu, acc, off);
    if (lane == 0) g_s1[r] = acc + b1[0];
}

__global__ void head_kernel(const float* __restrict__ w2, const float* __restrict__ b2,
                            const float* __restrict__ wo, const float* __restrict__ bo,
                            const float* __restrict__ wa, const float* __restrict__ ba,
                            float* __restrict__ out) {
    __shared__ float s1s[SEQ];
    __shared__ float s2s[50];
    int b = blockIdx.x, tid = threadIdx.x;
    for (int i = tid; i < SEQ; i += 64) s1s[i] = g_s1[b*SEQ + i];
    __syncthreads();
    if (tid < 50) {
        float acc = 0.0f;
        for (int s = 0; s < SEQ; s++) acc += s1s[s]*w2[s*50 + tid];
        s2s[tid] = gelu_f(acc + b2[tid]);
    }
    __syncthreads();
    if (tid < 7) {
        float acc = 0.0f;
        if (tid == 0) {
            for (int i = 0; i < 50; i++) acc += s2s[i]*wo[i];
            out[b*7] = acc + bo[0];
        } else {
            int j = tid - 1;
            for (int i = 0; i < 50; i++) acc += s2s[i]*wa[i*6 + j];
            out[b*7 + tid] = acc + ba[j];
        }
    }
}

// ---------------- launch ------------------------------------------------------
extern "C" void kernel_launch(void* const* d_in, const int* in_sizes, int n_in,
                              void* d_out, int out_size) {
    const int*   x_tok  = (const int*)  d_in[0];
    const float* emb    = (const float*)d_in[1];
    const float* qkv_w  = (const float*)d_in[2];
    const float* qkv_b  = (const float*)d_in[3];
    const float* out_w  = (const float*)d_in[4];
    const float* out_b  = (const float*)d_in[5];
    const float* ln1_s  = (const float*)d_in[6];
    const float* ln1_b  = (const float*)d_in[7];
    const float* ff1_w  = (const float*)d_in[8];
    const float* ff1_b  = (const float*)d_in[9];
    const float* ff2_w  = (const float*)d_in[10];
    const float* ff2_b  = (const float*)d_in[11];
    const float* ln2_s  = (const float*)d_in[12];
    const float* ln2_b  = (const float*)d_in[13];
    const float* lin1_w = (const float*)d_in[14];
    const float* lin1_b = (const float*)d_in[15];
    const float* lin2_w = (const float*)d_in[16];
    const float* lin2_b = (const float*)d_in[17];
    const float* lout_w = (const float*)d_in[18];
    const float* lout_b = (const float*)d_in[19];
    const float* laux_w = (const float*)d_in[20];
    const float* laux_b = (const float*)d_in[21];

    float *p_h, *p_h1, *p_prj, *p_ff2;
    __nv_bfloat16 *p_qkvb, *p_hb, *p_h1b, *p_att, *p_ff1;
    uint32_t *p_wqkv, *p_wprj, *p_wff1, *p_wff2;
    unsigned char *p_mask;
    cudaGetSymbolAddress((void**)&p_h,    g_h);
    cudaGetSymbolAddress((void**)&p_h1,   g_h1);
    cudaGetSymbolAddress((void**)&p_prj,  g_prj);
    cudaGetSymbolAddress((void**)&p_ff2,  g_ff2);
    cudaGetSymbolAddress((void**)&p_qkvb, g_qkvb);
    cudaGetSymbolAddress((void**)&p_hb,   g_hb);
    cudaGetSymbolAddress((void**)&p_h1b,  g_h1b);
    cudaGetSymbolAddress((void**)&p_att,  g_att);
    cudaGetSymbolAddress((void**)&p_ff1,  g_ff1);
    cudaGetSymbolAddress((void**)&p_mask, g_mask);
    cudaGetSymbolAddress((void**)&p_wqkv, g_pw_qkv);
    cudaGetSymbolAddress((void**)&p_wprj, g_pw_prj);
    cudaGetSymbolAddress((void**)&p_wff1, g_pw_ff1);
    cudaGetSymbolAddress((void**)&p_wff2, g_pw_ff2);

    cudaFuncSetAttribute(attn_kernel, cudaFuncAttributeMaxDynamicSharedMemorySize,
                         ATTN_SMEM);
    cudaFuncSetAttribute(mma_gemm_kernel, cudaFuncAttributeMaxDynamicSharedMemorySize,
                         GEMM_SMEM);

    sin_table_kernel<<<(SEQ*DIM + 255)/256, 256>>>();
    embed_kernel<<<(NROW*DIM + 255)/256, 256>>>(x_tok, emb);
    {
        int total = 5*(QKV_W + PRJ_W + FF1_W + FF2_W);
        pack_all_kernel<<<(total + 255)/256, 256>>>(qkv_w, out_w, ff1_w, ff2_w);
    }

    for (int l = 0; l < 5; l++) {
        mma_gemm_kernel<<<dim3(8, NROW/BM), 256, GEMM_SMEM>>>(p_hb,
            p_wqkv + (size_t)l*QKV_W, qkv_b + l*900, p_qkvb,
            900, 320, LDH, 1024, 900, 0, 1);
        attn_kernel<<<dim3(4, BATCH*NHEAD), 256, ATTN_SMEM>>>(p_qkvb, p_mask, p_att);
        mma_gemm_kernel<<<dim3(3, NROW/BM), 256, GEMM_SMEM>>>(p_att,
            p_wprj + (size_t)l*PRJ_W, out_b + l*DIM, p_prj,
            300, 320, LDH, 384, LDH, 0, 0);
        ln_kernel<<<NROW/8, 256>>>(p_h, p_prj, ln1_s + l*DIM, ln1_b + l*DIM,
                                   p_h1, p_h1b, nullptr);
        mma_gemm_kernel<<<dim3(5, NROW/BM), 256, GEMM_SMEM>>>(p_h1b,
            p_wff1 + (size_t)l*FF1_W, ff1_b + l*2*DIM, p_ff1,
            600, 320, LDH, 640, LDF, 1, 1);
        mma_gemm_kernel<<<dim3(3, NROW/BM), 256, GEMM_SMEM>>>(p_ff1,
            p_wff2 + (size_t)l*FF2_W, ff2_b + l*DIM, p_ff2,
            300, 608, LDF, 384, LDH, 0, 0);
        ln_kernel<<<NROW/8, 256>>>(p_h1, p_ff2, ln2_s + l*DIM, ln2_b + l*DIM,
                                   p_h, p_hb, p_mask);
    }

    rowdot_kernel<<<NROW/8, 256>>>(lin1_w, lin1_b);
    head_kernel<<<BATCH, 64>>>(lin2_w, lin2_b, lout_w, lout_b, laux_w, laux_b,
                               (float*)d_out);
}

// round 15
// speedup vs baseline: 1.4960x; 1.0661x over previous
#include <cuda_runtime.h>
#include <cuda_bf16.h>
#include <math.h>
#include <stdint.h>

// Problem constants
#define BATCH 256
#define SEQ   200
#define DIM   300
#define NHEAD 6
#define DHEAD 50
#define NROW  (BATCH*SEQ)        // 51200
#define LDH   320
#define LDF   608
#define GELU_C 0.7978845608028654f

// ---------------- scratch (device globals; zero-initialized) ------------------
__device__ float g_sin[SEQ*DIM];
__device__ float g_h  [NROW*LDH];
__device__ float g_h1 [NROW*LDH];
__device__ float g_prj[NROW*LDH];
__device__ float g_ff2[NROW*LDH];
__device__ float g_s1 [NROW];
__device__ unsigned char g_mask[NROW];

__device__ __nv_bfloat16 g_qkvb[NROW*900];
__device__ __nv_bfloat16 g_hb [NROW*LDH];
__device__ __nv_bfloat16 g_h1b[NROW*LDH];
__device__ __nv_bfloat16 g_att[NROW*LDH];
__device__ __nv_bfloat16 g_ff1[NROW*LDF];

// packed bf16 weights
#define QKV_W (160*1024)
#define PRJ_W (160*384)
#define FF1_W (160*640)
#define FF2_W (304*384)
__device__ uint32_t g_pw_qkv[5*QKV_W];
__device__ uint32_t g_pw_prj[5*PRJ_W];
__device__ uint32_t g_pw_ff1[5*FF1_W];
__device__ uint32_t g_pw_ff2[5*FF2_W];

__device__ __forceinline__ float gelu_f(float x) {
    float x3 = x*x*x;
    return 0.5f*x*(1.0f + tanhf(GELU_C*(x + 0.044715f*x3)));
}
__device__ __forceinline__ uint32_t smemu32(const void* p) {
    return (uint32_t)__cvta_generic_to_shared(p);
}
#define CP16(dst, src) asm volatile("cp.async.cg.shared.global [%0], [%1], 16;\n" :: "r"(dst), "l"(src))
#define CP_COMMIT()    asm volatile("cp.async.commit_group;\n" ::)
#define CP_WAIT(N)     asm volatile("cp.async.wait_group %0;\n" :: "n"(N))

#define MMA_BF16(acc, a0,a1,a2,a3, b0,b1) \
    asm volatile( \
        "mma.sync.aligned.m16n8k16.row.col.f32.bf16.bf16.f32 " \
        "{%0,%1,%2,%3}, {%4,%5,%6,%7}, {%8,%9}, {%0,%1,%2,%3};" \
        : "+f"((acc)[0]), "+f"((acc)[1]), "+f"((acc)[2]), "+f"((acc)[3]) \
        : "r"(a0), "r"(a1), "r"(a2), "r"(a3), "r"(b0), "r"(b1))

// ---------------- sinusoid table ----------------------------------------------
__global__ void sin_table_kernel() {
    int idx = blockIdx.x*blockDim.x + threadIdx.x;
    if (idx >= SEQ*DIM) return;
    int pos = idx / DIM, i = idx % DIM;
    double ang = (double)pos / pow(10000.0, 2.0*(double)(i/2)/(double)DIM);
    g_sin[idx] = (float)((i & 1) ? cos(ang) : sin(ang));
}

// ---------------- embedding + pos-enc + initial mask --------------------------
__global__ void embed_kernel(const int* __restrict__ tok,
                             const float* __restrict__ emb) {
    int idx = blockIdx.x*blockDim.x + threadIdx.x;
    if (idx >= NROW*DIM) return;
    int r = idx / DIM, d = idx % DIM;
    int t = tok[r];
    float v = emb[(size_t)t*DIM + d];
    if (t != 0) v += g_sin[(r % SEQ)*DIM + d];
    g_h [(size_t)r*LDH + d] = v;
    g_hb[(size_t)r*LDH + d] = __float2bfloat16_rn(v);
    if (d == 0) g_mask[r] = (t == 0) ? 1 : 0;
}

// ---------------- weight packing ----------------------------------------------
__device__ __forceinline__ void pack_bf(const float* __restrict__ src,
                                        uint32_t* __restrict__ dst, int i,
                                        int K, int N, int Kpw, int Np) {
    int per = Kpw*Np;
    int l = i / per, r = i % per;
    int kp = r / Np, n = r % Np;
    float f0 = (2*kp   < K && n < N) ? src[(size_t)l*K*N + (size_t)(2*kp  )*N + n] : 0.0f;
    float f1 = (2*kp+1 < K && n < N) ? src[(size_t)l*K*N + (size_t)(2*kp+1)*N + n] : 0.0f;
    __nv_bfloat162 p = __floats2bfloat162_rn(f0, f1);
    dst[i] = *reinterpret_cast<uint32_t*>(&p);
}
__global__ void pack_all_kernel(const float* __restrict__ qkv_w,
                                const float* __restrict__ out_w,
                                const float* __restrict__ ff1_w,
                                const float* __restrict__ ff2_w) {
    int i = blockIdx.x*blockDim.x + threadIdx.x;
    if (i < 5*QKV_W) { pack_bf(qkv_w, g_pw_qkv, i, 300, 900, 160, 1024); return; }
    i -= 5*QKV_W;
    if (i < 5*PRJ_W) { pack_bf(out_w, g_pw_prj, i, 300, 300, 160, 384); return; }
    i -= 5*PRJ_W;
    if (i < 5*FF1_W) { pack_bf(ff1_w, g_pw_ff1, i, 300, 600, 160, 640); return; }
    i -= 5*FF1_W;
    if (i < 5*FF2_W) { pack_bf(ff2_w, g_pw_ff2, i, 600, 300, 304, 384); return; }
}

// ---------------- BF16 tensor-core GEMM (5-stage, single-sync) ----------------
#define BM 128
#define BN 128
#define STAGES 5
#define ASTRIDE 20
#define BSTRIDE 136
#define A_ELEMS (BM*ASTRIDE)
#define B_ELEMS (16*BSTRIDE)
#define GEMM_SMEM ((STAGES*(A_ELEMS + B_ELEMS))*4)   // 94720 bytes

__global__ __launch_bounds__(256, 2) void mma_gemm_kernel(
        const __nv_bfloat16* __restrict__ A, const uint32_t* __restrict__ Bw,
        const float* __restrict__ bias, void* __restrict__ Cv,
        int N, int Kp, int lda, int Np, int ldc, int act, int obf) {
    extern __shared__ uint32_t dsm[];
    uint32_t* Asm = dsm;
    uint32_t* Bsm = dsm + STAGES*A_ELEMS;

    int tid = threadIdx.x;
    int warp = tid >> 5, lane = tid & 31;
    int g = lane >> 2, tig = lane & 3;
    int mw = (warp >> 2)*64, nw = (warp & 3)*32;
    int bm = blockIdx.y*BM, bn = blockIdx.x*BN;

    const __nv_bfloat16* Abase = A + (size_t)bm*lda;
    const uint32_t* Bbase = Bw + bn;

    float acc[4][4][4];
    #pragma unroll
    for (int i = 0; i < 4; i++)
        #pragma unroll
        for (int j = 0; j < 4; j++)
            #pragma unroll
            for (int r = 0; r < 4; r++) acc[i][j][r] = 0.0f;

    int nIter = Kp / 32;
    int am0 = tid >> 2,          awc0 = (tid & 3)*4;
    int am1 = (tid + 256) >> 2;
    int bk0 = tid >> 5,          bnc0 = (tid & 31)*4;
    int bk1 = (tid + 256) >> 5;

    auto loadStage = [&](int it, int s) {
        int k0e = it*32, k0w = it*16;
        uint32_t* As = Asm + s*A_ELEMS;
        uint32_t* Bs = Bsm + s*B_ELEMS;
        CP16(smemu32(&As[am0*ASTRIDE + awc0]), Abase + (size_t)am0*lda + k0e + awc0*2);
        CP16(smemu32(&As[am1*ASTRIDE + awc0]), Abase + (size_t)am1*lda + k0e + awc0*2);
        CP16(smemu32(&Bs[bk0*BSTRIDE + bnc0]), Bbase + (size_t)(k0w+bk0)*Np + bnc0);
        CP16(smemu32(&Bs[bk1*BSTRIDE + bnc0]), Bbase + (size_t)(k0w+bk1)*Np + bnc0);
    };

    #pragma unroll
    for (int s = 0; s < STAGES-1; s++) {
        loadStage(s, s);
        CP_COMMIT();
    }

    int cur = 0;
    for (int it = 0; it < nIter; it++) {
        CP_WAIT(STAGES-2);
        __syncthreads();

        const uint32_t* As = Asm + cur*A_ELEMS;
        const uint32_t* Bs = Bsm + cur*B_ELEMS;
        #pragma unroll
        for (int ks = 0; ks < 2; ks++) {
            int kb = ks*8;
            uint32_t af[4][4], bf[4][2];
            #pragma unroll
            for (int mt = 0; mt < 4; mt++) {
                int rm = mw + mt*16;
                af[mt][0] = As[(rm + g    )*ASTRIDE + kb + tig    ];
                af[mt][1] = As[(rm + g + 8)*ASTRIDE + kb + tig    ];
                af[mt][2] = As[(rm + g    )*ASTRIDE + kb + tig + 4];
                af[mt][3] = As[(rm + g + 8)*ASTRIDE + kb + tig + 4];
            }
            #pragma unroll
            for (int nt = 0; nt < 4; nt++) {
                int cn = nw + nt*8;
                bf[nt][0] = Bs[(kb + tig    )*BSTRIDE + cn + g];
                bf[nt][1] = Bs[(kb + tig + 4)*BSTRIDE + cn + g];
            }
            #pragma unroll
            for (int mt = 0; mt < 4; mt++)
                #pragma unroll
                for (int nt = 0; nt < 4; nt++)
                    MMA_BF16(acc[mt][nt], af[mt][0], af[mt][1], af[mt][2], af[mt][3],
                             bf[nt][0], bf[nt][1]);
        }

        if (it + STAGES-1 < nIter) {
            int s = (it + STAGES-1) % STAGES;
            loadStage(it + STAGES-1, s);
        }
        CP_COMMIT();
        cur = (cur + 1 == STAGES) ? 0 : cur + 1;
    }

    #pragma unroll
    for (int mt = 0; mt < 4; mt++) {
        int row0 = bm + mw + mt*16 + g;
        #pragma unroll
        for (int nt = 0; nt < 4; nt++) {
            int col = bn + nw + nt*8 + tig*2;
            if (col < N) {
                float b0 = bias[col], b1 = bias[col+1];
                float v0 = acc[mt][nt][0] + b0;
                float v1 = acc[mt][nt][1] + b1;
                float v2 = acc[mt][nt][2] + b0;
                float v3 = acc[mt][nt][3] + b1;
                if (act == 1) { v0 = gelu_f(v0); v1 = gelu_f(v1); v2 = gelu_f(v2); v3 = gelu_f(v3); }
                if (obf) {
                    __nv_bfloat16* C16 = (__nv_bfloat16*)Cv;
                    __nv_bfloat162 pa = __floats2bfloat162_rn(v0, v1);
                    __nv_bfloat162 pb = __floats2bfloat162_rn(v2, v3);
                    *(__nv_bfloat162*)&C16[(size_t)row0*ldc + col]     = pa;
                    *(__nv_bfloat162*)&C16[(size_t)(row0+8)*ldc + col] = pb;
                } else {
                    float* C = (float*)Cv;
                    *(float2*)&C[(size_t)row0*ldc + col]     = make_float2(v0, v1);
                    *(float2*)&C[(size_t)(row0+8)*ldc + col] = make_float2(v2, v3);
                }
            }
        }
    }
}

// ---------------- bf16 attention: double-buffered tiles, 1 sync/tile ----------
#define AQS 36
#define TBS 72
#define PSS 212
#define PBS 108
#define AQ_E (64*AQS)
#define TB_E (32*TBS)
#define PS_E (64*PSS)
#define PB_E (64*PBS)
#define ATTN_SMEM ((AQ_E + 2*TB_E + PS_E + PB_E + 64)*4 + 256)

__global__ __launch_bounds__(256, 2) void attn_kernel(
        const __nv_bfloat16* __restrict__ qkv,
        const unsigned char* __restrict__ mask,
        __nv_bfloat16* __restrict__ out) {
    extern __shared__ uint32_t smw[];
    uint32_t* Qs  = smw;
    uint32_t* Tb0 = Qs + AQ_E;                 // tile buffers [2]
    float*    Ps  = (float*)(Tb0 + 2*TB_E);
    uint32_t* Pb  = (uint32_t*)(Ps + PS_E);
    float*    inv = (float*)(Pb + PB_E);
    unsigned char* mk = (unsigned char*)(inv + 64);

    int bh = blockIdx.y;
    int b = bh / NHEAD, h = bh % NHEAD;
    int qbase = blockIdx.x * 64;
    int tid = threadIdx.x;
    int warp = tid >> 5, lane = tid & 31;
    int g = lane >> 2, tig = lane & 3;
    int wm = (warp >> 1)*16;
    int wn = warp & 1;

    const float scale = 0.1414213562373095f;  // 1/sqrt(50)
    const uint32_t* qw = (const uint32_t*)qkv;
    size_t rowbase = (size_t)b*SEQ*450;

    int kdw  = tid & 31, kkey0 = tid >> 5;     // K: dw fixed, key = kkey0 + j*8
    int vd   = tid & 63, vkw0  = tid >> 6;     // V: d fixed,  kw  = vkw0 + j*4

    uint32_t pre[8];

    auto loadK = [&](int kt) {
        int K0 = kt*64;
        #pragma unroll
        for (int j = 0; j < 8; j++) {
            int key = kkey0 + j*8;
            pre[j] = (kdw < 25 && K0 + key < SEQ)
                   ? qw[rowbase + (size_t)(K0+key)*450 + 150 + h*25 + kdw] : 0u;
        }
    };
    auto storeK = [&](uint32_t* Tb) {
        #pragma unroll
        for (int j = 0; j < 8; j++)
            Tb[kdw*TBS + kkey0 + j*8] = pre[j];
    };
    auto loadV = [&](int kt) {
        int K0 = kt*64;
        #pragma unroll
        for (int j = 0; j < 8; j++) {
            int kw = vkw0 + j*4;
            uint32_t v = 0;
            if (vd < DHEAD) {
                int k0 = K0 + 2*kw, k1 = K0 + 2*kw + 1;
                uint32_t lo = (k0 < SEQ) ? *(const uint16_t*)(qkv + (size_t)(b*SEQ + k0)*900 + 600 + h*DHEAD + vd) : 0;
                uint32_t hi = (k1 < SEQ) ? *(const uint16_t*)(qkv + (size_t)(b*SEQ + k1)*900 + 600 + h*DHEAD + vd) : 0;
                v = lo | (hi << 16);
            }
            pre[j] = v;
        }
    };
    auto storeV = [&](uint32_t* Tb) {
        #pragma unroll
        for (int j = 0; j < 8; j++)
            Tb[(vkw0 + j*4)*TBS + vd] = pre[j];
    };

    if (tid < SEQ) mk[tid] = mask[b*SEQ + tid];
    int padcnt = __syncthreads_count(tid < SEQ && mask[b*SEQ + tid]);
    bool allpad = (padcnt == SEQ);

    // fill Q chunk; prefetch + store K tile 0 into buf0 (no readers yet)
    loadK(0);
    for (int i = tid; i < 64*32; i += 256) {
        int r = i >> 5, wc = i & 31;
        int q = qbase + r;
        uint32_t v = (wc < 25 && q < SEQ) ? qw[rowbase + (size_t)q*450 + h*25 + wc] : 0u;
        Qs[r*AQS + wc] = v;
    }
    storeK(Tb0);

    // ---- S = Q @ K^T: 4 tiles, ONE sync per tile ----
    for (int kt = 0; kt < 4; kt++) {
        __syncthreads();               // buf[kt&1] visible; iter kt-1 readers done
        if (kt < 3) loadK(kt + 1);
        else        loadV(0);

        const uint32_t* Tb = Tb0 + (kt & 1)*TB_E;
        float sacc[4][4];
        #pragma unroll
        for (int nt = 0; nt < 4; nt++)
            #pragma unroll
            for (int r = 0; r < 4; r++) sacc[nt][r] = 0.0f;
        #pragma unroll
        for (int ks = 0; ks < 4; ks++) {
            int kb = ks*8;
            uint32_t a0 = Qs[(wm + g    )*AQS + kb + tig    ];
            uint32_t a1 = Qs[(wm + g + 8)*AQS + kb + tig    ];
            uint32_t a2 = Qs[(wm + g    )*AQS + kb + tig + 4];
            uint32_t a3 = Qs[(wm + g + 8)*AQS + kb + tig + 4];
            #pragma unroll
            for (int nt = 0; nt < 4; nt++) {
                int cn = wn*32 + nt*8;
                uint32_t b0 = Tb[(kb + tig    )*TBS + cn + g];
                uint32_t b1 = Tb[(kb + tig + 4)*TBS + cn + g];
                MMA_BF16(sacc[nt], a0, a1, a2, a3, b0, b1);
            }
        }
        int K0 = kt*64;
        #pragma unroll
        for (int nt = 0; nt < 4; nt++) {
            int col = K0 + wn*32 + nt*8 + tig*2;
            if (col < 208) {
                *(float2*)&Ps[(wm + g    )*PSS + col] = make_float2(sacc[nt][0], sacc[nt][1]);
                *(float2*)&Ps[(wm + g + 8)*PSS + col] = make_float2(sacc[nt][2], sacc[nt][3]);
            }
        }
        // stage next tile into the other buffer (its readers finished at this
        // iteration's top barrier)
        if (kt < 3) storeK(Tb0 + ((kt + 1) & 1)*TB_E);
        else        storeV(Tb0);       // V tile 0 -> buf0 (last read in iter 2)
    }
    __syncthreads();                   // Ps + V0 stores visible

    // ---- fp32 softmax (scale folded); pack P to bf16 key-pair words ----
    {
        int row = tid >> 2, j = tid & 3;
        const float2* p2 = (const float2*)&Ps[row*PSS];
        float m = -INFINITY;
        for (int kw = j*26; kw < j*26 + 26; kw++) {
            float2 v = p2[kw];
            int ka = 2*kw, kb2 = 2*kw + 1;
            if (ka  < SEQ && !mk[ka])  m = fmaxf(m, v.x*scale);
            if (kb2 < SEQ && !mk[kb2]) m = fmaxf(m, v.y*scale);
        }
        m = fmaxf(m, __shfl_xor_sync(0xffffffffu, m, 1));
        m = fmaxf(m, __shfl_xor_sync(0xffffffffu, m, 2));
        float ssum = 0.0f;
        for (int kw = j*26; kw < j*26 + 26; kw++) {
            float2 v = p2[kw];
            int ka = 2*kw, kb2 = 2*kw + 1;
            float p0 = 0.0f, p1 = 0.0f;
            if (ka  < SEQ && !mk[ka])  { p0 = __expf(v.x*scale - m); ssum += p0; }
            if (kb2 < SEQ && !mk[kb2]) { p1 = __expf(v.y*scale - m); ssum += p1; }
            __nv_bfloat162 pp = __floats2bfloat162_rn(p0, p1);
            Pb[row*PBS + kw] = *reinterpret_cast<uint32_t*>(&pp);
        }
        ssum += __shfl_xor_sync(0xffffffffu, ssum, 1);
        ssum += __shfl_xor_sync(0xffffffffu, ssum, 2);
        if (j == 0) inv[row] = (allpad || ssum == 0.0f) ? 0.0f : 1.0f/ssum;
    }
    __syncthreads();                   // Pb visible (V0 already in buf0)

    // ---- O = P @ V: 4 tiles, ONE sync per tile (first covered above) ----
    float oacc[4][4];
    #pragma unroll
    for (int nt = 0; nt < 4; nt++)
        #pragma unroll
        for (int r = 0; r < 4; r++) oacc[nt][r] = 0.0f;

    for (int kt = 0; kt < 4; kt++) {
        if (kt > 0) __syncthreads();   // buf[kt&1] stores visible; old readers done
        if (kt < 3) loadV(kt + 1);

        const uint32_t* Tb = Tb0 + (kt & 1)*TB_E;
        int K0w = kt*32;
        int nk = (kt == 3) ? 1 : 4;
        for (int ks = 0; ks < nk; ks++) {
            int kb = ks*8;
            uint32_t a0 = Pb[(wm + g    )*PBS + K0w + kb + tig    ];
            uint32_t a1 = Pb[(wm + g + 8)*PBS + K0w + kb + tig    ];
            uint32_t a2 = Pb[(wm + g    )*PBS + K0w + kb + tig + 4];
            uint32_t a3 = Pb[(wm + g + 8)*PBS + K0w + kb + tig + 4];
            #pragma unroll
            for (int nt = 0; nt < 4; nt++) {
                int cn = wn*32 + nt*8;
                uint32_t b0 = Tb[(kb + tig    )*TBS + cn + g];
                uint32_t b1 = Tb[(kb + tig + 4)*TBS + cn + g];
                MMA_BF16(oacc[nt], a0, a1, a2, a3, b0, b1);
            }
        }
        if (kt < 3) storeV(Tb0 + ((kt + 1) & 1)*TB_E);
    }

    // ---- epilogue: normalize + store bf16 ----
    {
        float v0 = inv[wm + g], v1 = inv[wm + g + 8];
        int q0 = qbase + wm + g;
        #pragma unroll
        for (int nt = 0; nt < 4; nt++) {
            int col = wn*32 + nt*8 + tig*2;
            if (col < DHEAD) {
                if (q0 < SEQ) {
                    __nv_bfloat162 p = __floats2bfloat162_rn(oacc[nt][0]*v0, oacc[nt][1]*v0);
                    *(__nv_bfloat162*)&out[(size_t)(b*SEQ + q0)*LDH + h*DHEAD + col] = p;
                }
                if (q0 + 8 < SEQ) {
                    __nv_bfloat162 p = __floats2bfloat162_rn(oacc[nt][2]*v1, oacc[nt][3]*v1);
                    *(__nv_bfloat162*)&out[(size_t)(b*SEQ + q0 + 8)*LDH + h*DHEAD + col] = p;
                }
            }
        }
    }
}

// ---------------- warp-per-row residual add + LayerNorm -----------------------
__global__ void ln_kernel(const float* __restrict__ X,
                          const float* __restrict__ Y,
                          const float* __restrict__ s,
                          const float* __restrict__ bcoef,
                          float* __restrict__ out,
                          __nv_bfloat16* __restrict__ outb,
                          unsigned char* maskout) {
    int tid = threadIdx.x, warp = tid >> 5, lane = tid & 31;
    int r = blockIdx.x*8 + warp;
    if (r >= NROW) return;

    float v[10]; int nd = 0;
    float sum = 0.0f;
    for (int d = lane; d < DIM; d += 32) {
        float t = X[(size_t)r*LDH + d] + Y[(size_t)r*LDH + d];
        v[nd++] = t;
        sum += t;
    }
    #pragma unroll
    for (int off = 16; off > 0; off >>= 1) sum += __shfl_xor_sync(0xffffffffu, sum, off);
    float mean = sum / (float)DIM;

    float var = 0.0f;
    for (int i = 0; i < nd; i++) { float d0 = v[i] - mean; var += d0*d0; }
    #pragma unroll
    for (int off = 16; off > 0; off >>= 1) var += __shfl_xor_sync(0xffffffffu, var, off);
    float rstd = 1.0f / sqrtf(var/(float)DIM + 1e-5f);

    bool allz = true;
    int i2 = 0;
    for (int d = lane; d < DIM; d += 32) {
        float o = (v[i2++] - mean)*rstd*s[d] + bcoef[d];
        out[(size_t)r*LDH + d] = o;
        outb[(size_t)r*LDH + d] = __float2bfloat16_rn(o);
        if (o != 0.0f) allz = false;
    }
    if (maskout) {
        bool all = __all_sync(0xffffffffu, allz);
        if (lane == 0) maskout[r] = all ? 1 : 0;
    }
}

// ---------------- head kernels ------------------------------------------------
__global__ void rowdot_kernel(const float* __restrict__ w1,
                              const float* __restrict__ b1) {
    int tid = threadIdx.x, warp = tid >> 5, lane = tid & 31;
    int r = blockIdx.x*8 + warp;
    if (r >= NROW) return;
    float acc = 0.0f;
    for (int d = lane; d < DIM; d += 32)
        acc += g_h[(size_t)r*LDH + d] * w1[d];
    #pragma unroll
    for (int off = 16; off > 0; off >>= 1) acc += __shfl_xor_sync(0xffffffffu, acc, off);
    if (lane == 0) g_s1[r] = acc + b1[0];
}

__global__ void head_kernel(const float* __restrict__ w2, const float* __restrict__ b2,
                            const float* __restrict__ wo, const float* __restrict__ bo,
                            const float* __restrict__ wa, const float* __restrict__ ba,
                            float* __restrict__ out) {
    __shared__ float s1s[SEQ];
    __shared__ float s2s[50];
    int b = blockIdx.x, tid = threadIdx.x;
    for (int i = tid; i < SEQ; i += 64) s1s[i] = g_s1[b*SEQ + i];
    __syncthreads();
    if (tid < 50) {
        float acc = 0.0f;
        for (int s = 0; s < SEQ; s++) acc += s1s[s]*w2[s*50 + tid];
        s2s[tid] = gelu_f(acc + b2[tid]);
    }
    __syncthreads();
    if (tid < 7) {
        float acc = 0.0f;
        if (tid == 0) {
            for (int i = 0; i < 50; i++) acc += s2s[i]*wo[i];
            out[b*7] = acc + bo[0];
        } else {
            int j = tid - 1;
            for (int i = 0; i < 50; i++) acc += s2s[i]*wa[i*6 + j];
            out[b*7 + tid] = acc + ba[j];
        }
    }
}

// ---------------- launch ------------------------------------------------------
extern "C" void kernel_launch(void* const* d_in, const int* in_sizes, int n_in,
                              void* d_out, int out_size) {
    const int*   x_tok  = (const int*)  d_in[0];
    const float* emb    = (const float*)d_in[1];
    const float* qkv_w  = (const float*)d_in[2];
    const float* qkv_b  = (const float*)d_in[3];
    const float* out_w  = (const float*)d_in[4];
    const float* out_b  = (const float*)d_in[5];
    const float* ln1_s  = (const float*)d_in[6];
    const float* ln1_b  = (const float*)d_in[7];
    const float* ff1_w  = (const float*)d_in[8];
    const float* ff1_b  = (const float*)d_in[9];
    const float* ff2_w  = (const float*)d_in[10];
    const float* ff2_b  = (const float*)d_in[11];
    const float* ln2_s  = (const float*)d_in[12];
    const float* ln2_b  = (const float*)d_in[13];
    const float* lin1_w = (const float*)d_in[14];
    const float* lin1_b = (const float*)d_in[15];
    const float* lin2_w = (const float*)d_in[16];
    const float* lin2_b = (const float*)d_in[17];
    const float* lout_w = (const float*)d_in[18];
    const float* lout_b = (const float*)d_in[19];
    const float* laux_w = (const float*)d_in[20];
    const float* laux_b = (const float*)d_in[21];

    float *p_h, *p_h1, *p_prj, *p_ff2;
    __nv_bfloat16 *p_qkvb, *p_hb, *p_h1b, *p_att, *p_ff1;
    uint32_t *p_wqkv, *p_wprj, *p_wff1, *p_wff2;
    unsigned char *p_mask;
    cudaGetSymbolAddress((void**)&p_h,    g_h);
    cudaGetSymbolAddress((void**)&p_h1,   g_h1);
    cudaGetSymbolAddress((void**)&p_prj,  g_prj);
    cudaGetSymbolAddress((void**)&p_ff2,  g_ff2);
    cudaGetSymbolAddress((void**)&p_qkvb, g_qkvb);
    cudaGetSymbolAddress((void**)&p_hb,   g_hb);
    cudaGetSymbolAddress((void**)&p_h1b,  g_h1b);
    cudaGetSymbolAddress((void**)&p_att,  g_att);
    cudaGetSymbolAddress((void**)&p_ff1,  g_ff1);
    cudaGetSymbolAddress((void**)&p_mask, g_mask);
    cudaGetSymbolAddress((void**)&p_wqkv, g_pw_qkv);
    cudaGetSymbolAddress((void**)&p_wprj, g_pw_prj);
    cudaGetSymbolAddress((void**)&p_wff1, g_pw_ff1);
    cudaGetSymbolAddress((void**)&p_wff2, g_pw_ff2);

    cudaFuncSetAttribute(attn_kernel, cudaFuncAttributeMaxDynamicSharedMemorySize,
                         ATTN_SMEM);
    cudaFuncSetAttribute(mma_gemm_kernel, cudaFuncAttributeMaxDynamicSharedMemorySize,
                         GEMM_SMEM);

    sin_table_kernel<<<(SEQ*DIM + 255)/256, 256>>>();
    embed_kernel<<<(NROW*DIM + 255)/256, 256>>>(x_tok, emb);
    {
        int total = 5*(QKV_W + PRJ_W + FF1_W + FF2_W);
        pack_all_kernel<<<(total + 255)/256, 256>>>(qkv_w, out_w, ff1_w, ff2_w);
    }

    for (int l = 0; l < 5; l++) {
        mma_gemm_kernel<<<dim3(8, NROW/BM), 256, GEMM_SMEM>>>(p_hb,
            p_wqkv + (size_t)l*QKV_W, qkv_b + l*900, p_qkvb,
            900, 320, LDH, 1024, 900, 0, 1);
        attn_kernel<<<dim3(4, BATCH*NHEAD), 256, ATTN_SMEM>>>(p_qkvb, p_mask, p_att);
        mma_gemm_kernel<<<dim3(3, NROW/BM), 256, GEMM_SMEM>>>(p_att,
            p_wprj + (size_t)l*PRJ_W, out_b + l*DIM, p_prj,
            300, 320, LDH, 384, LDH, 0, 0);
        ln_kernel<<<NROW/8, 256>>>(p_h, p_prj, ln1_s + l*DIM, ln1_b + l*DIM,
                                   p_h1, p_h1b, nullptr);
        mma_gemm_kernel<<<dim3(5, NROW/BM), 256, GEMM_SMEM>>>(p_h1b,
            p_wff1 + (size_t)l*FF1_W, ff1_b + l*2*DIM, p_ff1,
            600, 320, LDH, 640, LDF, 1, 1);
        mma_gemm_kernel<<<dim3(3, NROW/BM), 256, GEMM_SMEM>>>(p_ff1,
            p_wff2 + (size_t)l*FF2_W, ff2_b + l*DIM, p_ff2,
            300, 608, LDF, 384, LDH, 0, 0);
        ln_kernel<<<NROW/8, 256>>>(p_h1, p_ff2, ln2_s + l*DIM, ln2_b + l*DIM,
                                   p_h, p_hb, p_mask);
    }

    rowdot_kernel<<<NROW/8, 256>>>(lin1_w, lin1_b);
    head_kernel<<<BATCH, 64>>>(lin2_w, lin2_b, lout_w, lout_b, laux_w, laux_b,
                               (float*)d_out);
}

// round 16
// speedup vs baseline: 1.5439x; 1.0321x over previous
#include <cuda_runtime.h>
#include <cuda_bf16.h>
#include <math.h>
#include <stdint.h>

// Problem constants
#define BATCH 256
#define SEQ   200
#define DIM   300
#define NHEAD 6
#define DHEAD 50
#define NROW  (BATCH*SEQ)        // 51200
#define LDH   320
#define LDF   608
#define GELU_C 0.7978845608028654f

// ---------------- scratch (device globals; zero-initialized) ------------------
__device__ float g_sin[SEQ*DIM];
__device__ float g_h  [NROW*LDH];
__device__ float g_h1 [NROW*LDH];
__device__ float g_prj[NROW*LDH];
__device__ float g_ff2[NROW*LDH];
__device__ float g_s1 [NROW];
__device__ unsigned char g_mask[NROW];

__device__ __nv_bfloat16 g_qkvb[NROW*900];
__device__ __nv_bfloat16 g_hb [NROW*LDH];
__device__ __nv_bfloat16 g_h1b[NROW*LDH];
__device__ __nv_bfloat16 g_att[NROW*LDH];
__device__ __nv_bfloat16 g_ff1[NROW*LDF];

// packed bf16 weights, fragment-major stage blocks (see pack_bf)
#define QKV_W (160*1024)
#define PRJ_W (160*384)
#define FF1_W (160*640)
#define FF2_W (304*384)
__device__ uint32_t g_pw_qkv[5*QKV_W];
__device__ uint32_t g_pw_prj[5*PRJ_W];
__device__ uint32_t g_pw_ff1[5*FF1_W];
__device__ uint32_t g_pw_ff2[5*FF2_W];

__device__ __forceinline__ float gelu_f(float x) {
    float x3 = x*x*x;
    return 0.5f*x*(1.0f + tanhf(GELU_C*(x + 0.044715f*x3)));
}
__device__ __forceinline__ uint32_t smemu32(const void* p) {
    return (uint32_t)__cvta_generic_to_shared(p);
}
#define CP16(dst, src) asm volatile("cp.async.cg.shared.global [%0], [%1], 16;\n" :: "r"(dst), "l"(src))
#define CP_COMMIT()    asm volatile("cp.async.commit_group;\n" ::)
#define CP_WAIT(N)     asm volatile("cp.async.wait_group %0;\n" :: "n"(N))

#define MMA_BF16(acc, a0,a1,a2,a3, b0,b1) \
    asm volatile( \
        "mma.sync.aligned.m16n8k16.row.col.f32.bf16.bf16.f32 " \
        "{%0,%1,%2,%3}, {%4,%5,%6,%7}, {%8,%9}, {%0,%1,%2,%3};" \
        : "+f"((acc)[0]), "+f"((acc)[1]), "+f"((acc)[2]), "+f"((acc)[3]) \
        : "r"(a0), "r"(a1), "r"(a2), "r"(a3), "r"(b0), "r"(b1))

#define LDSM_X4(r0,r1,r2,r3, addr) \
    asm volatile("ldmatrix.sync.aligned.m8n8.x4.shared.b16 {%0,%1,%2,%3}, [%4];" \
        : "=r"(r0), "=r"(r1), "=r"(r2), "=r"(r3) : "r"(addr))

// ---------------- sinusoid table ----------------------------------------------
__global__ void sin_table_kernel() {
    int idx = blockIdx.x*blockDim.x + threadIdx.x;
    if (idx >= SEQ*DIM) return;
    int pos = idx / DIM, i = idx % DIM;
    double ang = (double)pos / pow(10000.0, 2.0*(double)(i/2)/(double)DIM);
    g_sin[idx] = (float)((i & 1) ? cos(ang) : sin(ang));
}

// ---------------- embedding + pos-enc + initial mask --------------------------
__global__ void embed_kernel(const int* __restrict__ tok,
                             const float* __restrict__ emb) {
    int idx = blockIdx.x*blockDim.x + threadIdx.x;
    if (idx >= NROW*DIM) return;
    int r = idx / DIM, d = idx % DIM;
    int t = tok[r];
    float v = emb[(size_t)t*DIM + d];
    if (t != 0) v += g_sin[(r % SEQ)*DIM + d];
    g_h [(size_t)r*LDH + d] = v;
    g_hb[(size_t)r*LDH + d] = __float2bfloat16_rn(v);
    if (d == 0) g_mask[r] = (t == 0) ? 1 : 0;
}

// ---------------- weight packing: frag-major stage blocks ---------------------
// Layout per layer: [stage s][col-block bb][2048 words], where within a block:
// word addr = (ks*128 + col)*8 + tig*2 + j  holds  kword kp = s*16+ks*8+j*4+tig,
// n = bb*128+col, value {B[2kp][n], B[2kp+1][n]}.
__device__ __forceinline__ void pack_bf(const float* __restrict__ src,
                                        uint32_t* __restrict__ dst, int i,
                                        int K, int N, int Kpw, int Np) {
    int nb = Np >> 7;
    int per_layer = Kpw*Np;                 // == (Kpw/16)*nb*2048
    int l = i / per_layer, r = i % per_layer;
    int per_stage = nb*2048;
    int s = r / per_stage; int r1 = r % per_stage;
    int bb = r1 >> 11;     int r2 = r1 & 2047;
    int j = r2 & 1;        int pairidx = r2 >> 1;
    int tig = pairidx & 3; int colks = pairidx >> 2;
    int col = colks & 127; int ks = colks >> 7;
    int kp = s*16 + ks*8 + j*4 + tig;
    int n = bb*128 + col;
    float f0 = (2*kp   < K && n < N) ? src[(size_t)l*K*N + (size_t)(2*kp  )*N + n] : 0.0f;
    float f1 = (2*kp+1 < K && n < N) ? src[(size_t)l*K*N + (size_t)(2*kp+1)*N + n] : 0.0f;
    __nv_bfloat162 p = __floats2bfloat162_rn(f0, f1);
    dst[i] = *reinterpret_cast<uint32_t*>(&p);
}
__global__ void pack_all_kernel(const float* __restrict__ qkv_w,
                                const float* __restrict__ out_w,
                                const float* __restrict__ ff1_w,
                                const float* __restrict__ ff2_w) {
    int i = blockIdx.x*blockDim.x + threadIdx.x;
    if (i < 5*QKV_W) { pack_bf(qkv_w, g_pw_qkv, i, 300, 900, 160, 1024); return; }
    i -= 5*QKV_W;
    if (i < 5*PRJ_W) { pack_bf(out_w, g_pw_prj, i, 300, 300, 160, 384); return; }
    i -= 5*PRJ_W;
    if (i < 5*FF1_W) { pack_bf(ff1_w, g_pw_ff1, i, 300, 600, 160, 640); return; }
    i -= 5*FF1_W;
    if (i < 5*FF2_W) { pack_bf(ff2_w, g_pw_ff2, i, 600, 300, 304, 384); return; }
}

// ---------------- BF16 GEMM: 5-stage, ldmatrix A, frag-major B ----------------
#define BM 128
#define BN 128
#define STAGES 5
#define ASTRIDE 20
#define A_ELEMS (BM*ASTRIDE)     // 2560 words
#define B_ELEMS 2048             // words per stage (frag-major, no padding)
#define GEMM_SMEM ((STAGES*(A_ELEMS + B_ELEMS))*4)   // 92160 bytes

__global__ __launch_bounds__(256, 2) void mma_gemm_kernel(
        const __nv_bfloat16* __restrict__ A, const uint32_t* __restrict__ Bw,
        const float* __restrict__ bias, void* __restrict__ Cv,
        int N, int Kp, int lda, int nb, int ldc, int act, int obf) {
    extern __shared__ uint32_t dsm[];
    uint32_t* Asm = dsm;
    uint32_t* Bsm = dsm + STAGES*A_ELEMS;

    int tid = threadIdx.x;
    int warp = tid >> 5, lane = tid & 31;
    int g = lane >> 2, tig = lane & 3;
    int mw = (warp >> 2)*64, nw = (warp & 3)*32;
    int bm = blockIdx.y*BM;
    int bx = blockIdx.x;

    const __nv_bfloat16* Abase = A + (size_t)bm*lda;

    // ldmatrix per-lane source coords within a 16x16 A tile
    int sub = lane >> 3, lr = lane & 7;
    int arow = (sub & 1)*8 + lr;     // row offset in tile
    int akw  = (sub >> 1)*4;         // kword offset in tile

    float acc[4][4][4];
    #pragma unroll
    for (int i = 0; i < 4; i++)
        #pragma unroll
        for (int j = 0; j < 4; j++)
            #pragma unroll
            for (int r = 0; r < 4; r++) acc[i][j][r] = 0.0f;

    int nIter = Kp / 32;
    int am0 = tid >> 2,          awc0 = (tid & 3)*4;
    int am1 = (tid + 256) >> 2;

    auto loadStage = [&](int it, int s) {
        int k0e = it*32;
        uint32_t* As = Asm + s*A_ELEMS;
        uint32_t* Bs = Bsm + s*B_ELEMS;
        CP16(smemu32(&As[am0*ASTRIDE + awc0]), Abase + (size_t)am0*lda + k0e + awc0*2);
        CP16(smemu32(&As[am1*ASTRIDE + awc0]), Abase + (size_t)am1*lda + k0e + awc0*2);
        const uint32_t* Bstage = Bw + ((size_t)it*nb + bx)*2048;
        CP16(smemu32(&Bs[tid*4]),         Bstage + tid*4);
        CP16(smemu32(&Bs[(tid+256)*4]),   Bstage + (tid+256)*4);
    };

    #pragma unroll
    for (int s = 0; s < STAGES-1; s++) {
        loadStage(s, s);
        CP_COMMIT();
    }

    int cur = 0;
    for (int it = 0; it < nIter; it++) {
        CP_WAIT(STAGES-2);
        __syncthreads();

        const uint32_t* As = Asm + cur*A_ELEMS;
        const uint2* Bp2 = (const uint2*)(Bsm + cur*B_ELEMS);
        uint32_t abase = smemu32(As);
        #pragma unroll
        for (int ks = 0; ks < 2; ks++) {
            uint32_t af[4][4], bf[4][2];
            #pragma unroll
            for (int mt = 0; mt < 4; mt++) {
                uint32_t addr = abase + (((mw + mt*16 + arow)*ASTRIDE + ks*8 + akw) << 2);
                LDSM_X4(af[mt][0], af[mt][1], af[mt][2], af[mt][3], addr);
            }
            #pragma unroll
            for (int nt = 0; nt < 4; nt++) {
                uint2 bp = Bp2[(ks*128 + nw + nt*8 + g)*4 + tig];
                bf[nt][0] = bp.x; bf[nt][1] = bp.y;
            }
            #pragma unroll
            for (int mt = 0; mt < 4; mt++)
                #pragma unroll
                for (int nt = 0; nt < 4; nt++)
                    MMA_BF16(acc[mt][nt], af[mt][0], af[mt][1], af[mt][2], af[mt][3],
                             bf[nt][0], bf[nt][1]);
        }

        if (it + STAGES-1 < nIter) {
            int s = (it + STAGES-1) % STAGES;
            loadStage(it + STAGES-1, s);
        }
        CP_COMMIT();
        cur = (cur + 1 == STAGES) ? 0 : cur + 1;
    }

    int bn = bx*BN;
    #pragma unroll
    for (int mt = 0; mt < 4; mt++) {
        int row0 = bm + mw + mt*16 + g;
        #pragma unroll
        for (int nt = 0; nt < 4; nt++) {
            int col = bn + nw + nt*8 + tig*2;
            if (col < N) {
                float b0 = bias[col], b1 = bias[col+1];
                float v0 = acc[mt][nt][0] + b0;
                float v1 = acc[mt][nt][1] + b1;
                float v2 = acc[mt][nt][2] + b0;
                float v3 = acc[mt][nt][3] + b1;
                if (act == 1) { v0 = gelu_f(v0); v1 = gelu_f(v1); v2 = gelu_f(v2); v3 = gelu_f(v3); }
                if (obf) {
                    __nv_bfloat16* C16 = (__nv_bfloat16*)Cv;
                    __nv_bfloat162 pa = __floats2bfloat162_rn(v0, v1);
                    __nv_bfloat162 pb = __floats2bfloat162_rn(v2, v3);
                    *(__nv_bfloat162*)&C16[(size_t)row0*ldc + col]     = pa;
                    *(__nv_bfloat162*)&C16[(size_t)(row0+8)*ldc + col] = pb;
                } else {
                    float* C = (float*)Cv;
                    *(float2*)&C[(size_t)row0*ldc + col]     = make_float2(v0, v1);
                    *(float2*)&C[(size_t)(row0+8)*ldc + col] = make_float2(v2, v3);
                }
            }
        }
    }
}

// ---------------- bf16 attention: double-buffered tiles, 1 sync/tile ----------
#define AQS 36
#define TBS 72
#define PSS 212
#define PBS 108
#define AQ_E (64*AQS)
#define TB_E (32*TBS)
#define PS_E (64*PSS)
#define PB_E (64*PBS)
#define ATTN_SMEM ((AQ_E + 2*TB_E + PS_E + PB_E + 64)*4 + 256)

__global__ __launch_bounds__(256, 2) void attn_kernel(
        const __nv_bfloat16* __restrict__ qkv,
        const unsigned char* __restrict__ mask,
        __nv_bfloat16* __restrict__ out) {
    extern __shared__ uint32_t smw[];
    uint32_t* Qs  = smw;
    uint32_t* Tb0 = Qs + AQ_E;
    float*    Ps  = (float*)(Tb0 + 2*TB_E);
    uint32_t* Pb  = (uint32_t*)(Ps + PS_E);
    float*    inv = (float*)(Pb + PB_E);
    unsigned char* mk = (unsigned char*)(inv + 64);

    int bh = blockIdx.y;
    int b = bh / NHEAD, h = bh % NHEAD;
    int qbase = blockIdx.x * 64;
    int tid = threadIdx.x;
    int warp = tid >> 5, lane = tid & 31;
    int g = lane >> 2, tig = lane & 3;
    int wm = (warp >> 1)*16;
    int wn = warp & 1;

    const float scale = 0.1414213562373095f;  // 1/sqrt(50)
    const uint32_t* qw = (const uint32_t*)qkv;
    size_t rowbase = (size_t)b*SEQ*450;

    int kdw  = tid & 31, kkey0 = tid >> 5;
    int vd   = tid & 63, vkw0  = tid >> 6;

    uint32_t pre[8];

    auto loadK = [&](int kt) {
        int K0 = kt*64;
        #pragma unroll
        for (int j = 0; j < 8; j++) {
            int key = kkey0 + j*8;
            pre[j] = (kdw < 25 && K0 + key < SEQ)
                   ? qw[rowbase + (size_t)(K0+key)*450 + 150 + h*25 + kdw] : 0u;
        }
    };
    auto storeK = [&](uint32_t* Tb) {
        #pragma unroll
        for (int j = 0; j < 8; j++)
            Tb[kdw*TBS + kkey0 + j*8] = pre[j];
    };
    auto loadV = [&](int kt) {
        int K0 = kt*64;
        #pragma unroll
        for (int j = 0; j < 8; j++) {
            int kw = vkw0 + j*4;
            uint32_t v = 0;
            if (vd < DHEAD) {
                int k0 = K0 + 2*kw, k1 = K0 + 2*kw + 1;
                uint32_t lo = (k0 < SEQ) ? *(const uint16_t*)(qkv + (size_t)(b*SEQ + k0)*900 + 600 + h*DHEAD + vd) : 0;
                uint32_t hi = (k1 < SEQ) ? *(const uint16_t*)(qkv + (size_t)(b*SEQ + k1)*900 + 600 + h*DHEAD + vd) : 0;
                v = lo | (hi << 16);
            }
            pre[j] = v;
        }
    };
    auto storeV = [&](uint32_t* Tb) {
        #pragma unroll
        for (int j = 0; j < 8; j++)
            Tb[(vkw0 + j*4)*TBS + vd] = pre[j];
    };

    if (tid < SEQ) mk[tid] = mask[b*SEQ + tid];
    int padcnt = __syncthreads_count(tid < SEQ && mask[b*SEQ + tid]);
    bool allpad = (padcnt == SEQ);

    loadK(0);
    for (int i = tid; i < 64*32; i += 256) {
        int r = i >> 5, wc = i & 31;
        int q = qbase + r;
        uint32_t v = (wc < 25 && q < SEQ) ? qw[rowbase + (size_t)q*450 + h*25 + wc] : 0u;
        Qs[r*AQS + wc] = v;
    }
    storeK(Tb0);

    for (int kt = 0; kt < 4; kt++) {
        __syncthreads();
        if (kt < 3) loadK(kt + 1);
        else        loadV(0);

        const uint32_t* Tb = Tb0 + (kt & 1)*TB_E;
        float sacc[4][4];
        #pragma unroll
        for (int nt = 0; nt < 4; nt++)
            #pragma unroll
            for (int r = 0; r < 4; r++) sacc[nt][r] = 0.0f;
        #pragma unroll
        for (int ks = 0; ks < 4; ks++) {
            int kb = ks*8;
            uint32_t a0 = Qs[(wm + g    )*AQS + kb + tig    ];
            uint32_t a1 = Qs[(wm + g + 8)*AQS + kb + tig    ];
            uint32_t a2 = Qs[(wm + g    )*AQS + kb + tig + 4];
            uint32_t a3 = Qs[(wm + g + 8)*AQS + kb + tig + 4];
            #pragma unroll
            for (int nt = 0; nt < 4; nt++) {
                int cn = wn*32 + nt*8;
                uint32_t b0 = Tb[(kb + tig    )*TBS + cn + g];
                uint32_t b1 = Tb[(kb + tig + 4)*TBS + cn + g];
                MMA_BF16(sacc[nt], a0, a1, a2, a3, b0, b1);
            }
        }
        int K0 = kt*64;
        #pragma unroll
        for (int nt = 0; nt < 4; nt++) {
            int col = K0 + wn*32 + nt*8 + tig*2;
            if (col < 208) {
                *(float2*)&Ps[(wm + g    )*PSS + col] = make_float2(sacc[nt][0], sacc[nt][1]);
                *(float2*)&Ps[(wm + g + 8)*PSS + col] = make_float2(sacc[nt][2], sacc[nt][3]);
            }
        }
        if (kt < 3) storeK(Tb0 + ((kt + 1) & 1)*TB_E);
        else        storeV(Tb0);
    }
    __syncthreads();

    {
        int row = tid >> 2, j = tid & 3;
        const float2* p2 = (const float2*)&Ps[row*PSS];
        float m = -INFINITY;
        for (int kw = j*26; kw < j*26 + 26; kw++) {
            float2 v = p2[kw];
            int ka = 2*kw, kb2 = 2*kw + 1;
            if (ka  < SEQ && !mk[ka])  m = fmaxf(m, v.x*scale);
            if (kb2 < SEQ && !mk[kb2]) m = fmaxf(m, v.y*scale);
        }
        m = fmaxf(m, __shfl_xor_sync(0xffffffffu, m, 1));
        m = fmaxf(m, __shfl_xor_sync(0xffffffffu, m, 2));
        float ssum = 0.0f;
        for (int kw = j*26; kw < j*26 + 26; kw++) {
            float2 v = p2[kw];
            int ka = 2*kw, kb2 = 2*kw + 1;
            float p0 = 0.0f, p1 = 0.0f;
            if (ka  < SEQ && !mk[ka])  { p0 = __expf(v.x*scale - m); ssum += p0; }
            if (kb2 < SEQ && !mk[kb2]) { p1 = __expf(v.y*scale - m); ssum += p1; }
            __nv_bfloat162 pp = __floats2bfloat162_rn(p0, p1);
            Pb[row*PBS + kw] = *reinterpret_cast<uint32_t*>(&pp);
        }
        ssum += __shfl_xor_sync(0xffffffffu, ssum, 1);
        ssum += __shfl_xor_sync(0xffffffffu, ssum, 2);
        if (j == 0) inv[row] = (allpad || ssum == 0.0f) ? 0.0f : 1.0f/ssum;
    }
    __syncthreads();

    float oacc[4][4];
    #pragma unroll
    for (int nt = 0; nt < 4; nt++)
        #pragma unroll
        for (int r = 0; r < 4; r++) oacc[nt][r] = 0.0f;

    for (int kt = 0; kt < 4; kt++) {
        if (kt > 0) __syncthreads();
        if (kt < 3) loadV(kt + 1);

        const uint32_t* Tb = Tb0 + (kt & 1)*TB_E;
        int K0w = kt*32;
        int nk = (kt == 3) ? 1 : 4;
        for (int ks = 0; ks < nk; ks++) {
            int kb = ks*8;
            uint32_t a0 = Pb[(wm + g    )*PBS + K0w + kb + tig    ];
            uint32_t a1 = Pb[(wm + g + 8)*PBS + K0w + kb + tig    ];
            uint32_t a2 = Pb[(wm + g    )*PBS + K0w + kb + tig + 4];
            uint32_t a3 = Pb[(wm + g + 8)*PBS + K0w + kb + tig + 4];
            #pragma unroll
            for (int nt = 0; nt < 4; nt++) {
                int cn = wn*32 + nt*8;
                uint32_t b0 = Tb[(kb + tig    )*TBS + cn + g];
                uint32_t b1 = Tb[(kb + tig + 4)*TBS + cn + g];
                MMA_BF16(oacc[nt], a0, a1, a2, a3, b0, b1);
            }
        }
        if (kt < 3) storeV(Tb0 + ((kt + 1) & 1)*TB_E);
    }

    {
        float v0 = inv[wm + g], v1 = inv[wm + g + 8];
        int q0 = qbase + wm + g;
        #pragma unroll
        for (int nt = 0; nt < 4; nt++) {
            int col = wn*32 + nt*8 + tig*2;
            if (col < DHEAD) {
                if (q0 < SEQ) {
                    __nv_bfloat162 p = __floats2bfloat162_rn(oacc[nt][0]*v0, oacc[nt][1]*v0);
                    *(__nv_bfloat162*)&out[(size_t)(b*SEQ + q0)*LDH + h*DHEAD + col] = p;
                }
                if (q0 + 8 < SEQ) {
                    __nv_bfloat162 p = __floats2bfloat162_rn(oacc[nt][2]*v1, oacc[nt][3]*v1);
                    *(__nv_bfloat162*)&out[(size_t)(b*SEQ + q0 + 8)*LDH + h*DHEAD + col] = p;
                }
            }
        }
    }
}

// ---------------- warp-per-row residual add + LayerNorm -----------------------
__global__ void ln_kernel(const float* __restrict__ X,
                          const float* __restrict__ Y,
                          const float* __restrict__ s,
                          const float* __restrict__ bcoef,
                          float* __restrict__ out,
                          __nv_bfloat16* __restrict__ outb,
                          unsigned char* maskout) {
    int tid = threadIdx.x, warp = tid >> 5, lane = tid & 31;
    int r = blockIdx.x*8 + warp;
    if (r >= NROW) return;

    float v[10]; int nd = 0;
    float sum = 0.0f;
    for (int d = lane; d < DIM; d += 32) {
        float t = X[(size_t)r*LDH + d] + Y[(size_t)r*LDH + d];
        v[nd++] = t;
        sum += t;
    }
    #pragma unroll
    for (int off = 16; off > 0; off >>= 1) sum += __shfl_xor_sync(0xffffffffu, sum, off);
    float mean = sum / (float)DIM;

    float var = 0.0f;
    for (int i = 0; i < nd; i++) { float d0 = v[i] - mean; var += d0*d0; }
    #pragma unroll
    for (int off = 16; off > 0; off >>= 1) var += __shfl_xor_sync(0xffffffffu, var, off);
    float rstd = 1.0f / sqrtf(var/(float)DIM + 1e-5f);

    bool allz = true;
    int i2 = 0;
    for (int d = lane; d < DIM; d += 32) {
        float o = (v[i2++] - mean)*rstd*s[d] + bcoef[d];
        out[(size_t)r*LDH + d] = o;
        outb[(size_t)r*LDH + d] = __float2bfloat16_rn(o);
        if (o != 0.0f) allz = false;
    }
    if (maskout) {
        bool all = __all_sync(0xffffffffu, allz);
        if (lane == 0) maskout[r] = all ? 1 : 0;
    }
}

// ---------------- head kernels ------------------------------------------------
__global__ void rowdot_kernel(const float* __restrict__ w1,
                              const float* __restrict__ b1) {
    int tid = threadIdx.x, warp = tid >> 5, lane = tid & 31;
    int r = blockIdx.x*8 + warp;
    if (r >= NROW) return;
    float acc = 0.0f;
    for (int d = lane; d < DIM; d += 32)
        acc += g_h[(size_t)r*LDH + d] * w1[d];
    #pragma unroll
    for (int off = 16; off > 0; off >>= 1) acc += __shfl_xor_sync(0xffffffffu, acc, off);
    if (lane == 0) g_s1[r] = acc + b1[0];
}

__global__ void head_kernel(const float* __restrict__ w2, const float* __restrict__ b2,
                            const float* __restrict__ wo, const float* __restrict__ bo,
                            const float* __restrict__ wa, const float* __restrict__ ba,
                            float* __restrict__ out) {
    __shared__ float s1s[SEQ];
    __shared__ float s2s[50];
    int b = blockIdx.x, tid = threadIdx.x;
    for (int i = tid; i < SEQ; i += 64) s1s[i] = g_s1[b*SEQ + i];
    __syncthreads();
    if (tid < 50) {
        float acc = 0.0f;
        for (int s = 0; s < SEQ; s++) acc += s1s[s]*w2[s*50 + tid];
        s2s[tid] = gelu_f(acc + b2[tid]);
    }
    __syncthreads();
    if (tid < 7) {
        float acc = 0.0f;
        if (tid == 0) {
            for (int i = 0; i < 50; i++) acc += s2s[i]*wo[i];
            out[b*7] = acc + bo[0];
        } else {
            int j = tid - 1;
            for (int i = 0; i < 50; i++) acc += s2s[i]*wa[i*6 + j];
            out[b*7 + tid] = acc + ba[j];
        }
    }
}

// ---------------- launch ------------------------------------------------------
extern "C" void kernel_launch(void* const* d_in, const int* in_sizes, int n_in,
                              void* d_out, int out_size) {
    const int*   x_tok  = (const int*)  d_in[0];
    const float* emb    = (const float*)d_in[1];
    const float* qkv_w  = (const float*)d_in[2];
    const float* qkv_b  = (const float*)d_in[3];
    const float* out_w  = (const float*)d_in[4];
    const float* out_b  = (const float*)d_in[5];
    const float* ln1_s  = (const float*)d_in[6];
    const float* ln1_b  = (const float*)d_in[7];
    const float* ff1_w  = (const float*)d_in[8];
    const float* ff1_b  = (const float*)d_in[9];
    const float* ff2_w  = (const float*)d_in[10];
    const float* ff2_b  = (const float*)d_in[11];
    const float* ln2_s  = (const float*)d_in[12];
    const float* ln2_b  = (const float*)d_in[13];
    const float* lin1_w = (const float*)d_in[14];
    const float* lin1_b = (const float*)d_in[15];
    const float* lin2_w = (const float*)d_in[16];
    const float* lin2_b = (const float*)d_in[17];
    const float* lout_w = (const float*)d_in[18];
    const float* lout_b = (const float*)d_in[19];
    const float* laux_w = (const float*)d_in[20];
    const float* laux_b = (const float*)d_in[21];

    float *p_h, *p_h1, *p_prj, *p_ff2;
    __nv_bfloat16 *p_qkvb, *p_hb, *p_h1b, *p_att, *p_ff1;
    uint32_t *p_wqkv, *p_wprj, *p_wff1, *p_wff2;
    unsigned char *p_mask;
    cudaGetSymbolAddress((void**)&p_h,    g_h);
    cudaGetSymbolAddress((void**)&p_h1,   g_h1);
    cudaGetSymbolAddress((void**)&p_prj,  g_prj);
    cudaGetSymbolAddress((void**)&p_ff2,  g_ff2);
    cudaGetSymbolAddress((void**)&p_qkvb, g_qkvb);
    cudaGetSymbolAddress((void**)&p_hb,   g_hb);
    cudaGetSymbolAddress((void**)&p_h1b,  g_h1b);
    cudaGetSymbolAddress((void**)&p_att,  g_att);
    cudaGetSymbolAddress((void**)&p_ff1,  g_ff1);
    cudaGetSymbolAddress((void**)&p_mask, g_mask);
    cudaGetSymbolAddress((void**)&p_wqkv, g_pw_qkv);
    cudaGetSymbolAddress((void**)&p_wprj, g_pw_prj);
    cudaGetSymbolAddress((void**)&p_wff1, g_pw_ff1);
    cudaGetSymbolAddress((void**)&p_wff2, g_pw_ff2);

    cudaFuncSetAttribute(attn_kernel, cudaFuncAttributeMaxDynamicSharedMemorySize,
                         ATTN_SMEM);
    cudaFuncSetAttribute(mma_gemm_kernel, cudaFuncAttributeMaxDynamicSharedMemorySize,
                         GEMM_SMEM);

    sin_table_kernel<<<(SEQ*DIM + 255)/256, 256>>>();
    embed_kernel<<<(NROW*DIM + 255)/256, 256>>>(x_tok, emb);
    {
        int total = 5*(QKV_W + PRJ_W + FF1_W + FF2_W);
        pack_all_kernel<<<(total + 255)/256, 256>>>(qkv_w, out_w, ff1_w, ff2_w);
    }

    for (int l = 0; l < 5; l++) {
        mma_gemm_kernel<<<dim3(8, NROW/BM), 256, GEMM_SMEM>>>(p_hb,
            p_wqkv + (size_t)l*QKV_W, qkv_b + l*900, p_qkvb,
            900, 320, LDH, 8, 900, 0, 1);
        attn_kernel<<<dim3(4, BATCH*NHEAD), 256, ATTN_SMEM>>>(p_qkvb, p_mask, p_att);
        mma_gemm_kernel<<<dim3(3, NROW/BM), 256, GEMM_SMEM>>>(p_att,
            p_wprj + (size_t)l*PRJ_W, out_b + l*DIM, p_prj,
            300, 320, LDH, 3, LDH, 0, 0);
        ln_kernel<<<NROW/8, 256>>>(p_h, p_prj, ln1_s + l*DIM, ln1_b + l*DIM,
                                   p_h1, p_h1b, nullptr);
        mma_gemm_kernel<<<dim3(5, NROW/BM), 256, GEMM_SMEM>>>(p_h1b,
            p_wff1 + (size_t)l*FF1_W, ff1_b + l*2*DIM, p_ff1,
            600, 320, LDH, 5, LDF, 1, 1);
        mma_gemm_kernel<<<dim3(3, NROW/BM), 256, GEMM_SMEM>>>(p_ff1,
            p_wff2 + (size_t)l*FF2_W, ff2_b + l*DIM, p_ff2,
            300, 608, LDF, 3, LDH, 0, 0);
        ln_kernel<<<NROW/8, 256>>>(p_h1, p_ff2, ln2_s + l*DIM, ln2_b + l*DIM,
                                   p_h, p_hb, p_mask);
    }

    rowdot_kernel<<<NROW/8, 256>>>(lin1_w, lin1_b);
    head_kernel<<<BATCH, 64>>>(lin2_w, lin2_b, lout_w, lout_b, laux_w, laux_b,
                               (float*)d_out);
}